// round 1
// baseline (speedup 1.0000x reference)
#include <cuda_runtime.h>
#include <cuda_bf16.h>
#include <math.h>

#define SQ   2048
#define DIM  512
#define NH   8
#define HDIM 64
#define NB   4
#define WIN  64
#define MROWS (NB * SQ)        // 8192
#define QKVD (3 * DIM)         // 1536
#define FFD  2048

// ---------------- scratch (static device allocations; no cudaMalloc) --------
__device__ float g_a  [(size_t)MROWS * DIM];
__device__ float g_qkv[(size_t)MROWS * QKVD];
__device__ float g_o  [(size_t)MROWS * DIM];
__device__ float g_x1 [(size_t)MROWS * DIM];
__device__ float g_f  [(size_t)MROWS * DIM];
__device__ float g_h  [(size_t)MROWS * FFD];

// ---------------- LayerNorm: one block (128 threads) per row of 512 --------
__global__ void ln_kernel(const float* __restrict__ x, const float* __restrict__ g,
                          const float* __restrict__ bb, float* __restrict__ out) {
    const int row = blockIdx.x;
    const int tid = threadIdx.x;                 // 128 threads, 4 floats each
    const float4* xr = (const float4*)(x + (size_t)row * DIM);
    float4 v = xr[tid];
    float s  = v.x + v.y + v.z + v.w;
    float ss = v.x*v.x + v.y*v.y + v.z*v.z + v.w*v.w;
    #pragma unroll
    for (int o = 16; o > 0; o >>= 1) {
        s  += __shfl_xor_sync(0xffffffffu, s,  o);
        ss += __shfl_xor_sync(0xffffffffu, ss, o);
    }
    __shared__ float as_[4], ass_[4];
    if ((tid & 31) == 0) { as_[tid >> 5] = s; ass_[tid >> 5] = ss; }
    __syncthreads();
    s  = as_[0] + as_[1] + as_[2] + as_[3];
    ss = ass_[0] + ass_[1] + ass_[2] + ass_[3];
    const float mean = s * (1.0f / DIM);
    const float var  = ss * (1.0f / DIM) - mean * mean;
    const float inv  = rsqrtf(var + 1e-5f);
    float4 gv = ((const float4*)g)[tid];
    float4 bv = ((const float4*)bb)[tid];
    float4 r;
    r.x = (v.x - mean) * inv * gv.x + bv.x;
    r.y = (v.y - mean) * inv * gv.y + bv.y;
    r.z = (v.z - mean) * inv * gv.z + bv.z;
    r.w = (v.w - mean) * inv * gv.w + bv.w;
    ((float4*)(out + (size_t)row * DIM))[tid] = r;
}

// ---------------- SGEMM: C[M,N] = A[M,K] @ W[N,K]^T  (+bias, epilogue) ------
// EPI: 0 = bias only, 1 = bias + exact GELU, 2 = bias + residual
__device__ __forceinline__ float gelu_exact(float v) {
    return 0.5f * v * (1.0f + erff(v * 0.70710678118654752f));
}

template <int EPI>
__global__ __launch_bounds__(256)
void sgemm(const float* __restrict__ A, const float* __restrict__ W,
           const float* __restrict__ bias, const float* __restrict__ R,
           float* __restrict__ C, int M, int N, int K) {
    __shared__ float As[8][128];
    __shared__ float Bs[8][128];
    const int tid = threadIdx.x;
    const int bm = blockIdx.y * 128;
    const int bn = blockIdx.x * 128;
    const int tx = tid & 15;       // 16 cols of threads
    const int ty = tid >> 4;       // 16 rows of threads
    const int lr = tid >> 1;       // loader row 0..127
    const int lc = (tid & 1) * 4;  // loader k offset 0 or 4

    const float* Ap = A + (size_t)(bm + lr) * K + lc;
    const float* Wp = W + (size_t)(bn + lr) * K + lc;

    float acc[8][8];
    #pragma unroll
    for (int i = 0; i < 8; i++)
        #pragma unroll
        for (int j = 0; j < 8; j++) acc[i][j] = 0.0f;

    for (int k0 = 0; k0 < K; k0 += 8) {
        float4 av = *(const float4*)(Ap + k0);
        float4 wv = *(const float4*)(Wp + k0);
        __syncthreads();
        As[lc + 0][lr] = av.x; As[lc + 1][lr] = av.y;
        As[lc + 2][lr] = av.z; As[lc + 3][lr] = av.w;
        Bs[lc + 0][lr] = wv.x; Bs[lc + 1][lr] = wv.y;
        Bs[lc + 2][lr] = wv.z; Bs[lc + 3][lr] = wv.w;
        __syncthreads();
        #pragma unroll
        for (int kk = 0; kk < 8; kk++) {
            float a[8], b[8];
            *(float4*)&a[0] = *(const float4*)&As[kk][ty * 8];
            *(float4*)&a[4] = *(const float4*)&As[kk][ty * 8 + 4];
            *(float4*)&b[0] = *(const float4*)&Bs[kk][tx * 8];
            *(float4*)&b[4] = *(const float4*)&Bs[kk][tx * 8 + 4];
            #pragma unroll
            for (int i = 0; i < 8; i++)
                #pragma unroll
                for (int j = 0; j < 8; j++) acc[i][j] += a[i] * b[j];
        }
    }

    // epilogue
    float bcol[8];
    #pragma unroll
    for (int j = 0; j < 8; j++) bcol[j] = bias[bn + tx * 8 + j];
    #pragma unroll
    for (int i = 0; i < 8; i++) {
        const size_t row = (size_t)(bm + ty * 8 + i);
        float* cp = C + row * N + bn + tx * 8;
        #pragma unroll
        for (int j = 0; j < 8; j++) {
            float v = acc[i][j] + bcol[j];
            if (EPI == 1) v = gelu_exact(v);
            if (EPI == 2) v += R[row * N + bn + tx * 8 + j];
            cp[j] = v;
        }
    }
}

// ---------------- Sparse local+global attention -----------------------------
// One block (128 threads) per (q, h, b). Keys: {0} U [q-64, q+64]; query 0
// attends to everything (row i==0 of glob mask). Softmax over computed set
// only (equivalent to full-row softmax with -inf elsewhere).
__global__ void attn_kernel(const float* __restrict__ qkv,
                            const unsigned char* __restrict__ pad,
                            float* __restrict__ o) {
    const int q = blockIdx.x, h = blockIdx.y, b = blockIdx.z;
    const int tid = threadIdx.x;  // 128

    __shared__ float qs[HDIM];
    __shared__ float sc[SQ];
    __shared__ float red[128];

    if (tid < HDIM)
        qs[tid] = qkv[((size_t)b * SQ + q) * QKVD + h * HDIM + tid];

    int kstart, kend;
    if (q == 0) { kstart = 0; kend = SQ - 1; }
    else {
        kstart = q - WIN; if (kstart < 0) kstart = 0;
        kend   = q + WIN; if (kend > SQ - 1) kend = SQ - 1;
    }
    const int hasg = (kstart > 0) ? 1 : 0;
    const int nk = kend - kstart + 1 + hasg;
    __syncthreads();

    const float4* qs4 = (const float4*)qs;
    for (int t = tid; t < nk; t += 128) {
        const int kj = (hasg && t == 0) ? 0 : kstart + t - hasg;
        const float4* kp = (const float4*)(qkv + ((size_t)b * SQ + kj) * QKVD + DIM + h * HDIM);
        float s = 0.0f;
        #pragma unroll
        for (int i = 0; i < 16; i++) {
            float4 kv = kp[i];
            float4 qv = qs4[i];
            s += qv.x * kv.x + qv.y * kv.y + qv.z * kv.z + qv.w * kv.w;
        }
        s *= 0.125f;                      // HD^-0.5
        if (pad[b * SQ + kj]) s = -1e30f; // key padding mask
        sc[t] = s;
    }
    __syncthreads();

    // block max
    float lm = -1e30f;
    for (int t = tid; t < nk; t += 128) lm = fmaxf(lm, sc[t]);
    red[tid] = lm;
    __syncthreads();
    for (int st = 64; st > 0; st >>= 1) {
        if (tid < st) red[tid] = fmaxf(red[tid], red[tid + st]);
        __syncthreads();
    }
    const float mx = red[0];
    __syncthreads();

    // exp + block sum
    float ls = 0.0f;
    for (int t = tid; t < nk; t += 128) {
        float e = expf(sc[t] - mx);
        sc[t] = e;
        ls += e;
    }
    red[tid] = ls;
    __syncthreads();
    for (int st = 64; st > 0; st >>= 1) {
        if (tid < st) red[tid] += red[tid + st];
        __syncthreads();
    }
    const float inv = 1.0f / red[0];

    // weighted sum of V: 64 threads, one output dim each (coalesced V reads)
    if (tid < HDIM) {
        float acc = 0.0f;
        for (int t = 0; t < nk; t++) {
            const int kj = (hasg && t == 0) ? 0 : kstart + t - hasg;
            acc += sc[t] * qkv[((size_t)b * SQ + kj) * QKVD + 2 * DIM + h * HDIM + tid];
        }
        o[((size_t)b * SQ + q) * DIM + h * HDIM + tid] = acc * inv;
    }
}

// ---------------- launch -----------------------------------------------------
extern "C" void kernel_launch(void* const* d_in, const int* in_sizes, int n_in,
                              void* d_out, int out_size) {
    const float* x   = (const float*)d_in[0];
    const unsigned char* pad = (const unsigned char*)d_in[1];
    // d_in[2] = attn_mask (structurally known; unused)
    const float* ipw = (const float*)d_in[3];
    const float* ipb = (const float*)d_in[4];
    const float* opw = (const float*)d_in[5];
    const float* opb = (const float*)d_in[6];
    const float* l1g = (const float*)d_in[7];
    const float* l1b = (const float*)d_in[8];
    const float* l2g = (const float*)d_in[9];
    const float* l2b = (const float*)d_in[10];
    const float* w1  = (const float*)d_in[11];
    const float* b1  = (const float*)d_in[12];
    const float* w2  = (const float*)d_in[13];
    const float* b2  = (const float*)d_in[14];
    float* out = (float*)d_out;

    float *a, *qkv, *o, *x1, *f, *hh;
    cudaGetSymbolAddress((void**)&a,   g_a);
    cudaGetSymbolAddress((void**)&qkv, g_qkv);
    cudaGetSymbolAddress((void**)&o,   g_o);
    cudaGetSymbolAddress((void**)&x1,  g_x1);
    cudaGetSymbolAddress((void**)&f,   g_f);
    cudaGetSymbolAddress((void**)&hh,  g_h);

    // 1. pre-LN for attention
    ln_kernel<<<MROWS, 128>>>(x, l1g, l1b, a);
    // 2. QKV projection  [8192,1536]
    sgemm<0><<<dim3(QKVD / 128, MROWS / 128), 256>>>(a, ipw, ipb, nullptr, qkv,
                                                     MROWS, QKVD, DIM);
    // 3. sparse local+global attention
    attn_kernel<<<dim3(SQ, NH, NB), 128>>>(qkv, pad, o);
    // 4. out projection + residual -> x1
    sgemm<2><<<dim3(DIM / 128, MROWS / 128), 256>>>(o, opw, opb, x, x1,
                                                    MROWS, DIM, DIM);
    // 5. pre-LN for FF
    ln_kernel<<<MROWS, 128>>>(x1, l2g, l2b, f);
    // 6. FF1 + exact GELU
    sgemm<1><<<dim3(FFD / 128, MROWS / 128), 256>>>(f, w1, b1, nullptr, hh,
                                                    MROWS, FFD, DIM);
    // 7. FF2 + residual -> final output
    sgemm<2><<<dim3(DIM / 128, MROWS / 128), 256>>>(hh, w2, b2, x1, out,
                                                    MROWS, DIM, FFD);
}

// round 2
// speedup vs baseline: 1.7424x; 1.7424x over previous
#include <cuda_runtime.h>
#include <cuda_bf16.h>
#include <math.h>
#include <stdint.h>

#define SQ   2048
#define DIM  512
#define NH   8
#define HDIM 64
#define NB   4
#define WIN  64
#define MROWS (NB * SQ)        // 8192
#define QKVD (3 * DIM)         // 1536
#define FFD  2048

// ---------------- scratch (static device allocations; no cudaMalloc) --------
__device__ float g_a  [(size_t)MROWS * DIM];
__device__ float g_qkv[(size_t)MROWS * QKVD];
__device__ float g_o  [(size_t)MROWS * DIM];
__device__ float g_x1 [(size_t)MROWS * DIM];
__device__ float g_f  [(size_t)MROWS * DIM];
__device__ float g_h  [(size_t)MROWS * FFD];

// ---------------- LayerNorm: one block (128 threads) per row of 512 --------
__global__ void ln_kernel(const float* __restrict__ x, const float* __restrict__ g,
                          const float* __restrict__ bb, float* __restrict__ out) {
    const int row = blockIdx.x;
    const int tid = threadIdx.x;                 // 128 threads, 4 floats each
    const float4* xr = (const float4*)(x + (size_t)row * DIM);
    float4 v = xr[tid];
    float s  = v.x + v.y + v.z + v.w;
    float ss = v.x*v.x + v.y*v.y + v.z*v.z + v.w*v.w;
    #pragma unroll
    for (int o = 16; o > 0; o >>= 1) {
        s  += __shfl_xor_sync(0xffffffffu, s,  o);
        ss += __shfl_xor_sync(0xffffffffu, ss, o);
    }
    __shared__ float as_[4], ass_[4];
    if ((tid & 31) == 0) { as_[tid >> 5] = s; ass_[tid >> 5] = ss; }
    __syncthreads();
    s  = as_[0] + as_[1] + as_[2] + as_[3];
    ss = ass_[0] + ass_[1] + ass_[2] + ass_[3];
    const float mean = s * (1.0f / DIM);
    const float var  = ss * (1.0f / DIM) - mean * mean;
    const float inv  = rsqrtf(var + 1e-5f);
    float4 gv = ((const float4*)g)[tid];
    float4 bv = ((const float4*)bb)[tid];
    float4 r;
    r.x = (v.x - mean) * inv * gv.x + bv.x;
    r.y = (v.y - mean) * inv * gv.y + bv.y;
    r.z = (v.z - mean) * inv * gv.z + bv.z;
    r.w = (v.w - mean) * inv * gv.w + bv.w;
    ((float4*)(out + (size_t)row * DIM))[tid] = r;
}

// ---------------- tf32 tensor-core GEMM ------------------------------------
// C[M,N] = A[M,K] @ W[N,K]^T (+bias, epilogue)
// EPI: 0 = bias only, 1 = bias + exact GELU, 2 = bias + residual

__device__ __forceinline__ float gelu_exact(float v) {
    return 0.5f * v * (1.0f + erff(v * 0.70710678118654752f));
}

__device__ __forceinline__ uint32_t f2tf32(float f) {
    uint32_t r;
    asm("cvt.rna.tf32.f32 %0, %1;" : "=r"(r) : "f"(f));
    return r;
}

__device__ __forceinline__ uint4 pack_tf32(float4 v) {
    uint4 u;
    u.x = f2tf32(v.x); u.y = f2tf32(v.y);
    u.z = f2tf32(v.z); u.w = f2tf32(v.w);
    return u;
}

__device__ __forceinline__ void mma_tf32(float* c, const uint32_t* a, const uint32_t* b) {
    asm volatile(
        "mma.sync.aligned.m16n8k8.row.col.f32.tf32.tf32.f32 "
        "{%0,%1,%2,%3}, {%4,%5,%6,%7}, {%8,%9}, {%0,%1,%2,%3};"
        : "+f"(c[0]), "+f"(c[1]), "+f"(c[2]), "+f"(c[3])
        : "r"(a[0]), "r"(a[1]), "r"(a[2]), "r"(a[3]), "r"(b[0]), "r"(b[1]));
}

#define LDK 36   // smem row stride in words (pad 32->36: conflict-free frags)

template <int EPI>
__global__ __launch_bounds__(256)
void tgemm(const float* __restrict__ A, const float* __restrict__ W,
           const float* __restrict__ bias, const float* __restrict__ R,
           float* __restrict__ C, int M, int N, int K) {
    __shared__ uint32_t As[128 * LDK];
    __shared__ uint32_t Bs[128 * LDK];

    const int tid  = threadIdx.x;
    const int warp = tid >> 5;
    const int lane = tid & 31;
    const int g    = lane >> 2;   // 0..7
    const int t4   = lane & 3;    // 0..3
    const int wm   = warp >> 2;   // 0..1 -> 64 rows
    const int wn   = warp & 3;    // 0..3 -> 32 cols

    const int bm = blockIdx.y * 128;
    const int bn = blockIdx.x * 128;

    const int lrow = tid >> 1;            // 0..127
    const int lkof = (tid & 1) * 16;      // 0 or 16

    const float* Ap = A + (size_t)(bm + lrow) * K + lkof;
    const float* Wp = W + (size_t)(bn + lrow) * K + lkof;
    uint32_t* dstA = As + lrow * LDK + lkof;
    uint32_t* dstB = Bs + lrow * LDK + lkof;

    float acc[4][4][4];
    #pragma unroll
    for (int i = 0; i < 4; i++)
        #pragma unroll
        for (int j = 0; j < 4; j++)
            #pragma unroll
            for (int v = 0; v < 4; v++) acc[i][j][v] = 0.0f;

    const uint32_t* afb = As + (wm * 64 + g) * LDK;
    const uint32_t* bfb = Bs + (wn * 32 + g) * LDK;

    for (int k0 = 0; k0 < K; k0 += 32) {
        float4 av[4], wv[4];
        #pragma unroll
        for (int i = 0; i < 4; i++) {
            av[i] = *(const float4*)(Ap + k0 + i * 4);
            wv[i] = *(const float4*)(Wp + k0 + i * 4);
        }
        __syncthreads();
        #pragma unroll
        for (int i = 0; i < 4; i++) {
            *(uint4*)(dstA + i * 4) = pack_tf32(av[i]);
            *(uint4*)(dstB + i * 4) = pack_tf32(wv[i]);
        }
        __syncthreads();

        #pragma unroll
        for (int kk = 0; kk < 32; kk += 8) {
            uint32_t af[4][4], bf[4][2];
            #pragma unroll
            for (int mt = 0; mt < 4; mt++) {
                const uint32_t* p = afb + mt * (16 * LDK) + kk + t4;
                af[mt][0] = p[0];
                af[mt][1] = p[8 * LDK];
                af[mt][2] = p[4];
                af[mt][3] = p[8 * LDK + 4];
            }
            #pragma unroll
            for (int nt = 0; nt < 4; nt++) {
                const uint32_t* p = bfb + nt * (8 * LDK) + kk + t4;
                bf[nt][0] = p[0];
                bf[nt][1] = p[4];
            }
            #pragma unroll
            for (int mt = 0; mt < 4; mt++)
                #pragma unroll
                for (int nt = 0; nt < 4; nt++)
                    mma_tf32(acc[mt][nt], af[mt], bf[nt]);
        }
    }

    // epilogue
    #pragma unroll
    for (int mt = 0; mt < 4; mt++) {
        const int r0 = bm + wm * 64 + mt * 16 + g;
        const int r1 = r0 + 8;
        #pragma unroll
        for (int nt = 0; nt < 4; nt++) {
            const int col = bn + wn * 32 + nt * 8 + 2 * t4;
            const float b0 = bias[col], b1 = bias[col + 1];
            float v0 = acc[mt][nt][0] + b0;
            float v1 = acc[mt][nt][1] + b1;
            float v2 = acc[mt][nt][2] + b0;
            float v3 = acc[mt][nt][3] + b1;
            if (EPI == 1) {
                v0 = gelu_exact(v0); v1 = gelu_exact(v1);
                v2 = gelu_exact(v2); v3 = gelu_exact(v3);
            }
            if (EPI == 2) {
                v0 += R[(size_t)r0 * N + col];
                v1 += R[(size_t)r0 * N + col + 1];
                v2 += R[(size_t)r1 * N + col];
                v3 += R[(size_t)r1 * N + col + 1];
            }
            C[(size_t)r0 * N + col]     = v0;
            C[(size_t)r0 * N + col + 1] = v1;
            C[(size_t)r1 * N + col]     = v2;
            C[(size_t)r1 * N + col + 1] = v3;
        }
    }
}

// ---------------- Sparse local+global attention -----------------------------
// One block (128 threads) per (q, h, b). Keys: {0} U [q-64, q+64]; query 0
// attends to everything (row i==0 of glob mask).
__global__ void attn_kernel(const float* __restrict__ qkv,
                            const unsigned char* __restrict__ pad,
                            float* __restrict__ o) {
    const int q = blockIdx.x, h = blockIdx.y, b = blockIdx.z;
    const int tid = threadIdx.x;  // 128

    __shared__ float qs[HDIM];
    __shared__ float sc[SQ];
    __shared__ float red[128];

    if (tid < HDIM)
        qs[tid] = qkv[((size_t)b * SQ + q) * QKVD + h * HDIM + tid];

    int kstart, kend;
    if (q == 0) { kstart = 0; kend = SQ - 1; }
    else {
        kstart = q - WIN; if (kstart < 0) kstart = 0;
        kend   = q + WIN; if (kend > SQ - 1) kend = SQ - 1;
    }
    const int hasg = (kstart > 0) ? 1 : 0;
    const int nk = kend - kstart + 1 + hasg;
    __syncthreads();

    const float4* qs4 = (const float4*)qs;
    for (int t = tid; t < nk; t += 128) {
        const int kj = (hasg && t == 0) ? 0 : kstart + t - hasg;
        const float4* kp = (const float4*)(qkv + ((size_t)b * SQ + kj) * QKVD + DIM + h * HDIM);
        float s = 0.0f;
        #pragma unroll
        for (int i = 0; i < 16; i++) {
            float4 kv = kp[i];
            float4 qv = qs4[i];
            s += qv.x * kv.x + qv.y * kv.y + qv.z * kv.z + qv.w * kv.w;
        }
        s *= 0.125f;                      // HD^-0.5
        if (pad[b * SQ + kj]) s = -1e30f; // key padding mask
        sc[t] = s;
    }
    __syncthreads();

    // block max
    float lm = -1e30f;
    for (int t = tid; t < nk; t += 128) lm = fmaxf(lm, sc[t]);
    red[tid] = lm;
    __syncthreads();
    for (int st = 64; st > 0; st >>= 1) {
        if (tid < st) red[tid] = fmaxf(red[tid], red[tid + st]);
        __syncthreads();
    }
    const float mx = red[0];
    __syncthreads();

    // exp + block sum
    float ls = 0.0f;
    for (int t = tid; t < nk; t += 128) {
        float e = expf(sc[t] - mx);
        sc[t] = e;
        ls += e;
    }
    red[tid] = ls;
    __syncthreads();
    for (int st = 64; st > 0; st >>= 1) {
        if (tid < st) red[tid] += red[tid + st];
        __syncthreads();
    }
    const float inv = 1.0f / red[0];
    __syncthreads();

    // weighted sum of V: 128 threads = 64 dims x 2 key-halves
    {
        const int d = tid & 63;
        const int half = tid >> 6;
        float acc = 0.0f;
        for (int t = half; t < nk; t += 2) {
            const int kj = (hasg && t == 0) ? 0 : kstart + t - hasg;
            acc += sc[t] * qkv[((size_t)b * SQ + kj) * QKVD + 2 * DIM + h * HDIM + d];
        }
        red[tid] = acc;
    }
    __syncthreads();
    if (tid < HDIM) {
        o[((size_t)b * SQ + q) * DIM + h * HDIM + tid] =
            (red[tid] + red[tid + 64]) * inv;
    }
}

// ---------------- launch -----------------------------------------------------
extern "C" void kernel_launch(void* const* d_in, const int* in_sizes, int n_in,
                              void* d_out, int out_size) {
    const float* x   = (const float*)d_in[0];
    const unsigned char* pad = (const unsigned char*)d_in[1];
    // d_in[2] = attn_mask (structurally known; unused)
    const float* ipw = (const float*)d_in[3];
    const float* ipb = (const float*)d_in[4];
    const float* opw = (const float*)d_in[5];
    const float* opb = (const float*)d_in[6];
    const float* l1g = (const float*)d_in[7];
    const float* l1b = (const float*)d_in[8];
    const float* l2g = (const float*)d_in[9];
    const float* l2b = (const float*)d_in[10];
    const float* w1  = (const float*)d_in[11];
    const float* b1  = (const float*)d_in[12];
    const float* w2  = (const float*)d_in[13];
    const float* b2  = (const float*)d_in[14];
    float* out = (float*)d_out;

    float *a, *qkv, *o, *x1, *f, *hh;
    cudaGetSymbolAddress((void**)&a,   g_a);
    cudaGetSymbolAddress((void**)&qkv, g_qkv);
    cudaGetSymbolAddress((void**)&o,   g_o);
    cudaGetSymbolAddress((void**)&x1,  g_x1);
    cudaGetSymbolAddress((void**)&f,   g_f);
    cudaGetSymbolAddress((void**)&hh,  g_h);

    // 1. pre-LN for attention
    ln_kernel<<<MROWS, 128>>>(x, l1g, l1b, a);
    // 2. QKV projection  [8192,1536]
    tgemm<0><<<dim3(QKVD / 128, MROWS / 128), 256>>>(a, ipw, ipb, nullptr, qkv,
                                                     MROWS, QKVD, DIM);
    // 3. sparse local+global attention
    attn_kernel<<<dim3(SQ, NH, NB), 128>>>(qkv, pad, o);
    // 4. out projection + residual -> x1
    tgemm<2><<<dim3(DIM / 128, MROWS / 128), 256>>>(o, opw, opb, x, x1,
                                                    MROWS, DIM, DIM);
    // 5. pre-LN for FF
    ln_kernel<<<MROWS, 128>>>(x1, l2g, l2b, f);
    // 6. FF1 + exact GELU
    tgemm<1><<<dim3(FFD / 128, MROWS / 128), 256>>>(f, w1, b1, nullptr, hh,
                                                    MROWS, FFD, DIM);
    // 7. FF2 + residual -> final output
    tgemm<2><<<dim3(DIM / 128, MROWS / 128), 256>>>(hh, w2, b2, x1, out,
                                                    MROWS, DIM, FFD);
}

// round 5
// speedup vs baseline: 2.8246x; 1.6211x over previous
#include <cuda_runtime.h>
#include <cuda_bf16.h>
#include <math.h>
#include <stdint.h>

#define SQ   2048
#define DIM  512
#define NH   8
#define HDIM 64
#define NB   4
#define WIN  64
#define MROWS (NB * SQ)        // 8192
#define QKVD (3 * DIM)         // 1536
#define FFD  2048

// ---------------- scratch (static device allocations; no cudaMalloc) --------
__device__ float g_a  [(size_t)MROWS * DIM];
__device__ float g_qkv[(size_t)MROWS * QKVD];
__device__ float g_o  [(size_t)MROWS * DIM];
__device__ float g_x1 [(size_t)MROWS * DIM];
__device__ float g_f  [(size_t)MROWS * DIM];
__device__ float g_h  [(size_t)MROWS * FFD];

// ---------------- LayerNorm: one block (128 threads) per row of 512 --------
__global__ void ln_kernel(const float* __restrict__ x, const float* __restrict__ g,
                          const float* __restrict__ bb, float* __restrict__ out) {
    const int row = blockIdx.x;
    const int tid = threadIdx.x;                 // 128 threads, 4 floats each
    const float4* xr = (const float4*)(x + (size_t)row * DIM);
    float4 v = xr[tid];
    float s  = v.x + v.y + v.z + v.w;
    float ss = v.x*v.x + v.y*v.y + v.z*v.z + v.w*v.w;
    #pragma unroll
    for (int o = 16; o > 0; o >>= 1) {
        s  += __shfl_xor_sync(0xffffffffu, s,  o);
        ss += __shfl_xor_sync(0xffffffffu, ss, o);
    }
    __shared__ float as_[4], ass_[4];
    if ((tid & 31) == 0) { as_[tid >> 5] = s; ass_[tid >> 5] = ss; }
    __syncthreads();
    s  = as_[0] + as_[1] + as_[2] + as_[3];
    ss = ass_[0] + ass_[1] + ass_[2] + ass_[3];
    const float mean = s * (1.0f / DIM);
    const float var  = ss * (1.0f / DIM) - mean * mean;
    const float inv  = rsqrtf(var + 1e-5f);
    float4 gv = ((const float4*)g)[tid];
    float4 bv = ((const float4*)bb)[tid];
    float4 r;
    r.x = (v.x - mean) * inv * gv.x + bv.x;
    r.y = (v.y - mean) * inv * gv.y + bv.y;
    r.z = (v.z - mean) * inv * gv.z + bv.z;
    r.w = (v.w - mean) * inv * gv.w + bv.w;
    ((float4*)(out + (size_t)row * DIM))[tid] = r;
}

// ---------------- tf32 tensor-core GEMM (proven in R2) -----------------------
__device__ __forceinline__ float gelu_exact(float v) {
    return 0.5f * v * (1.0f + erff(v * 0.70710678118654752f));
}

__device__ __forceinline__ uint32_t f2tf32(float f) {
    uint32_t r;
    asm("cvt.rna.tf32.f32 %0, %1;" : "=r"(r) : "f"(f));
    return r;
}

__device__ __forceinline__ uint4 pack_tf32(float4 v) {
    uint4 u;
    u.x = f2tf32(v.x); u.y = f2tf32(v.y);
    u.z = f2tf32(v.z); u.w = f2tf32(v.w);
    return u;
}

__device__ __forceinline__ void mma_tf32(float* c, const uint32_t* a, const uint32_t* b) {
    asm volatile(
        "mma.sync.aligned.m16n8k8.row.col.f32.tf32.tf32.f32 "
        "{%0,%1,%2,%3}, {%4,%5,%6,%7}, {%8,%9}, {%0,%1,%2,%3};"
        : "+f"(c[0]), "+f"(c[1]), "+f"(c[2]), "+f"(c[3])
        : "r"(a[0]), "r"(a[1]), "r"(a[2]), "r"(a[3]), "r"(b[0]), "r"(b[1]));
}

#define LDK 36   // smem row stride in words (pad 32->36: conflict-free frags)

template <int EPI>
__global__ __launch_bounds__(256)
void tgemm(const float* __restrict__ A, const float* __restrict__ W,
           const float* __restrict__ bias, const float* __restrict__ R,
           float* __restrict__ C, int M, int N, int K) {
    __shared__ uint32_t As[128 * LDK];
    __shared__ uint32_t Bs[128 * LDK];

    const int tid  = threadIdx.x;
    const int warp = tid >> 5;
    const int lane = tid & 31;
    const int g    = lane >> 2;   // 0..7
    const int t4   = lane & 3;    // 0..3
    const int wm   = warp >> 2;   // 0..1 -> 64 rows
    const int wn   = warp & 3;    // 0..3 -> 32 cols

    const int bm = blockIdx.y * 128;
    const int bn = blockIdx.x * 128;

    const int lrow = tid >> 1;            // 0..127
    const int lkof = (tid & 1) * 16;      // 0 or 16

    const float* Ap = A + (size_t)(bm + lrow) * K + lkof;
    const float* Wp = W + (size_t)(bn + lrow) * K + lkof;
    uint32_t* dstA = As + lrow * LDK + lkof;
    uint32_t* dstB = Bs + lrow * LDK + lkof;

    float acc[4][4][4];
    #pragma unroll
    for (int i = 0; i < 4; i++)
        #pragma unroll
        for (int j = 0; j < 4; j++)
            #pragma unroll
            for (int v = 0; v < 4; v++) acc[i][j][v] = 0.0f;

    const uint32_t* afb = As + (wm * 64 + g) * LDK;
    const uint32_t* bfb = Bs + (wn * 32 + g) * LDK;

    for (int k0 = 0; k0 < K; k0 += 32) {
        float4 av[4], wv[4];
        #pragma unroll
        for (int i = 0; i < 4; i++) {
            av[i] = *(const float4*)(Ap + k0 + i * 4);
            wv[i] = *(const float4*)(Wp + k0 + i * 4);
        }
        __syncthreads();
        #pragma unroll
        for (int i = 0; i < 4; i++) {
            *(uint4*)(dstA + i * 4) = pack_tf32(av[i]);
            *(uint4*)(dstB + i * 4) = pack_tf32(wv[i]);
        }
        __syncthreads();

        #pragma unroll
        for (int kk = 0; kk < 32; kk += 8) {
            uint32_t af[4][4], bf[4][2];
            #pragma unroll
            for (int mt = 0; mt < 4; mt++) {
                const uint32_t* p = afb + mt * (16 * LDK) + kk + t4;
                af[mt][0] = p[0];
                af[mt][1] = p[8 * LDK];
                af[mt][2] = p[4];
                af[mt][3] = p[8 * LDK + 4];
            }
            #pragma unroll
            for (int nt = 0; nt < 4; nt++) {
                const uint32_t* p = bfb + nt * (8 * LDK) + kk + t4;
                bf[nt][0] = p[0];
                bf[nt][1] = p[4];
            }
            #pragma unroll
            for (int mt = 0; mt < 4; mt++)
                #pragma unroll
                for (int nt = 0; nt < 4; nt++)
                    mma_tf32(acc[mt][nt], af[mt], bf[nt]);
        }
    }

    // epilogue
    #pragma unroll
    for (int mt = 0; mt < 4; mt++) {
        const int r0 = bm + wm * 64 + mt * 16 + g;
        const int r1 = r0 + 8;
        #pragma unroll
        for (int nt = 0; nt < 4; nt++) {
            const int col = bn + wn * 32 + nt * 8 + 2 * t4;
            const float b0 = bias[col], b1 = bias[col + 1];
            float v0 = acc[mt][nt][0] + b0;
            float v1 = acc[mt][nt][1] + b1;
            float v2 = acc[mt][nt][2] + b0;
            float v3 = acc[mt][nt][3] + b1;
            if (EPI == 1) {
                v0 = gelu_exact(v0); v1 = gelu_exact(v1);
                v2 = gelu_exact(v2); v3 = gelu_exact(v3);
            }
            if (EPI == 2) {
                v0 += R[(size_t)r0 * N + col];
                v1 += R[(size_t)r0 * N + col + 1];
                v2 += R[(size_t)r1 * N + col];
                v3 += R[(size_t)r1 * N + col + 1];
            }
            C[(size_t)r0 * N + col]     = v0;
            C[(size_t)r0 * N + col + 1] = v1;
            C[(size_t)r1 * N + col]     = v2;
            C[(size_t)r1 * N + col + 1] = v3;
        }
    }
}

// ---------------- Tiled local+global attention (fp32/tf32) -------------------
// Block = 32 queries x (h, b). Key slots: {0} U [q0-64, q0+31+64] (<=161).
// Scores via tf32 MMA on SMEM tiles; per-query window mask applied in softmax.
#define TQ   32
#define NKP  168   // slot capacity (21 n-tiles of 8)
#define LDA  68    // words per 64-wide row (64 + 4 pad)
#define SP   176   // score row stride (floats)
#define ATTN_SMEM ((32 * LDA + 2 * NKP * LDA) * 4 + 32 * SP * 4 + 176 + 128)

__global__ __launch_bounds__(256)
void attn_tile_kernel(const float* __restrict__ qkv,
                      const unsigned char* __restrict__ pad,
                      float* __restrict__ o) {
    extern __shared__ __align__(16) uint32_t sm[];
    uint32_t* Qs  = sm;                        // 32*LDA  (tf32)
    uint32_t* Ksm = Qs + 32 * LDA;             // NKP*LDA (tf32)
    float*    Vsm = (float*)(Ksm + NKP * LDA); // NKP*LDA (fp32)
    float*    Sf  = Vsm + NKP * LDA;           // 32*SP
    unsigned char* pads = (unsigned char*)(Sf + 32 * SP);  // 176 B
    float*    invs = (float*)(pads + 176);     // 32 floats

    const int q0 = blockIdx.x * TQ;
    const int h  = blockIdx.y;
    const int b  = blockIdx.z;
    const int tid  = threadIdx.x;
    const int warp = tid >> 5;
    const int lane = tid & 31;
    const int g    = lane >> 2;
    const int t4   = lane & 3;

    int ks = q0 - WIN; if (ks < 0) ks = 0;
    int ke = q0 + TQ - 1 + WIN; if (ke > SQ - 1) ke = SQ - 1;
    const int hasg = (ks > 0) ? 1 : 0;
    const int nk = ke - ks + 1 + hasg;           // <= 161
    const int ntmax = (nk + 7) >> 3;

    // ---- load tiles: 16 threads per row (float4 each) ----
    {
        const int lrow = tid >> 4;       // 0..15
        const int lcol = tid & 15;       // float4 index within 64-float row
        for (int r = lrow; r < TQ; r += 16) {
            float4 v = *(const float4*)(qkv + ((size_t)(b * SQ + q0 + r)) * QKVD
                                        + h * HDIM + lcol * 4);
            *(uint4*)(Qs + r * LDA + lcol * 4) = pack_tf32(v);
        }
        for (int j = lrow; j < nk; j += 16) {
            const int kj = (hasg && j == 0) ? 0 : ks + j - hasg;
            const float* base = qkv + ((size_t)(b * SQ + kj)) * QKVD;
            float4 kv = *(const float4*)(base + DIM + h * HDIM + lcol * 4);
            *(uint4*)(Ksm + j * LDA + lcol * 4) = pack_tf32(kv);
            float4 vv = *(const float4*)(base + 2 * DIM + h * HDIM + lcol * 4);
            *(float4*)(Vsm + j * LDA + lcol * 4) = vv;
            if (lcol == 0) pads[j] = pad[b * SQ + kj];
        }
    }
    __syncthreads();

    // ---- scores S[32][nk] = Q @ K^T (tf32 MMA) ----
    {
        const int mt   = warp & 1;       // m-tile of 16
        const int nset = warp >> 1;      // n-tile group 0..3
        uint32_t af[8][4];
        const uint32_t* afb = Qs + (mt * 16 + g) * LDA;
        #pragma unroll
        for (int kk = 0; kk < 8; kk++) {
            const uint32_t* p = afb + kk * 8 + t4;
            af[kk][0] = p[0];
            af[kk][1] = p[8 * LDA];
            af[kk][2] = p[4];
            af[kk][3] = p[8 * LDA + 4];
        }
        const uint32_t* bfb = Ksm + g * LDA;
        for (int nt = nset; nt < ntmax; nt += 4) {
            float c[4] = {0.f, 0.f, 0.f, 0.f};
            #pragma unroll
            for (int kk = 0; kk < 8; kk++) {
                const uint32_t* p = bfb + nt * (8 * LDA) + kk * 8 + t4;
                uint32_t bf[2] = { p[0], p[4] };
                mma_tf32(c, af[kk], bf);
            }
            const int r0 = mt * 16 + g;
            const int col = nt * 8 + 2 * t4;
            Sf[r0 * SP + col]           = c[0];
            Sf[r0 * SP + col + 1]       = c[1];
            Sf[(r0 + 8) * SP + col]     = c[2];
            Sf[(r0 + 8) * SP + col + 1] = c[3];
        }
    }
    __syncthreads();

    // ---- softmax rows (8 threads per query) with per-query window mask ----
    {
        const int q = tid >> 3, sub = tid & 7;
        const int qg = q0 + q;               // global query index
        float* Sr = Sf + q * SP;
        float mx = -1e30f;
        for (int j = sub; j < nk; j += 8) {
            const int kj = (hasg && j == 0) ? 0 : ks + j - hasg;
            float s = Sr[j] * 0.125f;
            const int d = kj - qg;
            const bool valid = (kj == 0) || (d >= -WIN && d <= WIN);
            if (!valid || pads[j]) s = -1e30f;
            Sr[j] = s;
            mx = fmaxf(mx, s);
        }
        #pragma unroll
        for (int off = 4; off > 0; off >>= 1)
            mx = fmaxf(mx, __shfl_xor_sync(0xffffffffu, mx, off, 8));
        float sum = 0.f;
        for (int j = sub; j < nk; j += 8) {
            float e = expf(Sr[j] - mx);
            Sr[j] = e;
            sum += e;
        }
        #pragma unroll
        for (int off = 4; off > 0; off >>= 1)
            sum += __shfl_xor_sync(0xffffffffu, sum, off, 8);
        if (sub == 0) invs[q] = 1.0f / sum;
    }
    __syncthreads();

    // ---- P @ V : thread = (q, 8-dim group) ----
    {
        const int q = tid >> 3, dg = tid & 7;
        float a0=0,a1=0,a2=0,a3=0,a4=0,a5=0,a6=0,a7=0;
        const float* Sr = Sf + q * SP;
        const float* Vb = Vsm + dg * 8;
        for (int j = 0; j < nk; j++) {
            const float p = Sr[j];
            float4 v0 = *(const float4*)(Vb + j * LDA);
            float4 v1 = *(const float4*)(Vb + j * LDA + 4);
            a0 += p * v0.x; a1 += p * v0.y; a2 += p * v0.z; a3 += p * v0.w;
            a4 += p * v1.x; a5 += p * v1.y; a6 += p * v1.z; a7 += p * v1.w;
        }
        const float inv = invs[q];
        float* op = o + ((size_t)(b * SQ + q0 + q)) * DIM + h * HDIM + dg * 8;
        float4 r0 = { a0 * inv, a1 * inv, a2 * inv, a3 * inv };
        float4 r1 = { a4 * inv, a5 * inv, a6 * inv, a7 * inv };
        *(float4*)op = r0;
        *(float4*)(op + 4) = r1;
    }
}

// ---------------- query-0 full-row attention (fp32) --------------------------
__global__ __launch_bounds__(256)
void attn_global_kernel(const float* __restrict__ qkv,
                        const unsigned char* __restrict__ pad,
                        float* __restrict__ o) {
    const int h = blockIdx.x, b = blockIdx.y;
    const int tid = threadIdx.x;
    __shared__ float qf[HDIM];
    __shared__ float S2[SQ];
    __shared__ float red[256];
    __shared__ float sinv;

    if (tid < HDIM)
        qf[tid] = qkv[((size_t)(b * SQ)) * QKVD + h * HDIM + tid];
    __syncthreads();

    const float4* qf4 = (const float4*)qf;
    for (int j = tid; j < SQ; j += 256) {
        const float4* kp = (const float4*)(qkv + ((size_t)(b * SQ + j)) * QKVD
                                           + DIM + h * HDIM);
        float s = 0.f;
        #pragma unroll
        for (int i = 0; i < 16; i++) {
            float4 kv = kp[i], qv = qf4[i];
            s += qv.x * kv.x + qv.y * kv.y + qv.z * kv.z + qv.w * kv.w;
        }
        s *= 0.125f;
        if (pad[b * SQ + j]) s = -1e30f;
        S2[j] = s;
    }
    __syncthreads();
    float mx = -1e30f;
    for (int j = tid; j < SQ; j += 256) mx = fmaxf(mx, S2[j]);
    red[tid] = mx; __syncthreads();
    for (int st = 128; st > 0; st >>= 1) {
        if (tid < st) red[tid] = fmaxf(red[tid], red[tid + st]);
        __syncthreads();
    }
    mx = red[0]; __syncthreads();
    float sum = 0.f;
    for (int j = tid; j < SQ; j += 256) {
        float e = expf(S2[j] - mx);
        S2[j] = e; sum += e;
    }
    red[tid] = sum; __syncthreads();
    for (int st = 128; st > 0; st >>= 1) {
        if (tid < st) red[tid] += red[tid + st];
        __syncthreads();
    }
    if (tid == 0) sinv = 1.0f / red[0];
    __syncthreads();
    const int d = tid & 63, grp = tid >> 6;
    float acc = 0.f;
    for (int j = grp; j < SQ; j += 4)
        acc += S2[j] * qkv[((size_t)(b * SQ + j)) * QKVD + 2 * DIM + h * HDIM + d];
    red[tid] = acc; __syncthreads();
    if (tid < HDIM) {
        o[((size_t)(b * SQ)) * DIM + h * HDIM + tid] =
            (red[tid] + red[tid + 64] + red[tid + 128] + red[tid + 192]) * sinv;
    }
}

// ---------------- launch -----------------------------------------------------
extern "C" void kernel_launch(void* const* d_in, const int* in_sizes, int n_in,
                              void* d_out, int out_size) {
    const float* x   = (const float*)d_in[0];
    const unsigned char* pad = (const unsigned char*)d_in[1];
    const float* ipw = (const float*)d_in[3];
    const float* ipb = (const float*)d_in[4];
    const float* opw = (const float*)d_in[5];
    const float* opb = (const float*)d_in[6];
    const float* l1g = (const float*)d_in[7];
    const float* l1b = (const float*)d_in[8];
    const float* l2g = (const float*)d_in[9];
    const float* l2b = (const float*)d_in[10];
    const float* w1  = (const float*)d_in[11];
    const float* b1  = (const float*)d_in[12];
    const float* w2  = (const float*)d_in[13];
    const float* b2  = (const float*)d_in[14];
    float* out = (float*)d_out;

    float *a, *qkv, *o, *x1, *f, *hh;
    cudaGetSymbolAddress((void**)&a,   g_a);
    cudaGetSymbolAddress((void**)&qkv, g_qkv);
    cudaGetSymbolAddress((void**)&o,   g_o);
    cudaGetSymbolAddress((void**)&x1,  g_x1);
    cudaGetSymbolAddress((void**)&f,   g_f);
    cudaGetSymbolAddress((void**)&hh,  g_h);

    cudaFuncSetAttribute(attn_tile_kernel,
                         cudaFuncAttributeMaxDynamicSharedMemorySize, ATTN_SMEM);

    // 1. pre-LN for attention
    ln_kernel<<<MROWS, 128>>>(x, l1g, l1b, a);
    // 2. QKV projection
    tgemm<0><<<dim3(QKVD / 128, MROWS / 128), 256>>>(a, ipw, ipb, nullptr, qkv,
                                                     MROWS, QKVD, DIM);
    // 3. attention: tiled local windows, then q==0 global fix-up
    attn_tile_kernel<<<dim3(SQ / TQ, NH, NB), 256, ATTN_SMEM>>>(qkv, pad, o);
    attn_global_kernel<<<dim3(NH, NB), 256>>>(qkv, pad, o);
    // 4. out projection + residual -> x1
    tgemm<2><<<dim3(DIM / 128, MROWS / 128), 256>>>(o, opw, opb, x, x1,
                                                    MROWS, DIM, DIM);
    // 5. pre-LN for FF
    ln_kernel<<<MROWS, 128>>>(x1, l2g, l2b, f);
    // 6. FF1 + exact GELU
    tgemm<1><<<dim3(FFD / 128, MROWS / 128), 256>>>(f, w1, b1, nullptr, hh,
                                                    MROWS, FFD, DIM);
    // 7. FF2 + residual -> final output
    tgemm<2><<<dim3(DIM / 128, MROWS / 128), 256>>>(hh, w2, b2, x1, out,
                                                    MROWS, DIM, FFD);
}

// round 6
// speedup vs baseline: 3.6541x; 1.2937x over previous
#include <cuda_runtime.h>
#include <cuda_fp16.h>
#include <math.h>
#include <stdint.h>

#define SQ   2048
#define DIM  512
#define NH   8
#define HDIM 64
#define NB   4
#define WIN  64
#define MROWS (NB * SQ)        // 8192
#define QKVD (3 * DIM)         // 1536
#define FFD  2048

// ---------------- scratch (static device allocations; no cudaMalloc) --------
__device__ float  g_a   [(size_t)MROWS * DIM];
__device__ __half g_qkvh[(size_t)MROWS * QKVD];
__device__ float  g_o   [(size_t)MROWS * DIM];
__device__ float  g_x1  [(size_t)MROWS * DIM];
__device__ float  g_f   [(size_t)MROWS * DIM];
__device__ float  g_h   [(size_t)MROWS * FFD];
// split-softmax partials for query-0 global attention
__device__ float  g_pm  [NB * NH * 8];
__device__ float  g_ps  [NB * NH * 8];
__device__ float  g_pa  [NB * NH * 8 * HDIM];

// ---------------- helpers ----------------------------------------------------
__device__ __forceinline__ uint32_t smem_u32(const void* p) {
    return (uint32_t)__cvta_generic_to_shared(p);
}
__device__ __forceinline__ void ldsm_x4(uint32_t* r, uint32_t addr) {
    asm volatile("ldmatrix.sync.aligned.m8n8.x4.shared.b16 {%0,%1,%2,%3}, [%4];\n"
        : "=r"(r[0]), "=r"(r[1]), "=r"(r[2]), "=r"(r[3]) : "r"(addr));
}
__device__ __forceinline__ void ldsm_x2(uint32_t* r, uint32_t addr) {
    asm volatile("ldmatrix.sync.aligned.m8n8.x2.shared.b16 {%0,%1}, [%2];\n"
        : "=r"(r[0]), "=r"(r[1]) : "r"(addr));
}
__device__ __forceinline__ void mma16816(float* c, const uint32_t* a, const uint32_t* b) {
    asm volatile(
        "mma.sync.aligned.m16n8k16.row.col.f32.f16.f16.f32 "
        "{%0,%1,%2,%3},{%4,%5,%6,%7},{%8,%9},{%0,%1,%2,%3};\n"
        : "+f"(c[0]), "+f"(c[1]), "+f"(c[2]), "+f"(c[3])
        : "r"(a[0]), "r"(a[1]), "r"(a[2]), "r"(a[3]), "r"(b[0]), "r"(b[1]));
}
__device__ __forceinline__ float gelu_exact(float v) {
    return 0.5f * v * (1.0f + erff(v * 0.70710678118654752f));
}
__device__ __forceinline__ uint32_t f2tf32(float f) {
    uint32_t r;
    asm("cvt.rna.tf32.f32 %0, %1;" : "=r"(r) : "f"(f));
    return r;
}
__device__ __forceinline__ uint4 pack_tf32(float4 v) {
    uint4 u;
    u.x = f2tf32(v.x); u.y = f2tf32(v.y);
    u.z = f2tf32(v.z); u.w = f2tf32(v.w);
    return u;
}
__device__ __forceinline__ void mma_tf32(float* c, const uint32_t* a, const uint32_t* b) {
    asm volatile(
        "mma.sync.aligned.m16n8k8.row.col.f32.tf32.tf32.f32 "
        "{%0,%1,%2,%3}, {%4,%5,%6,%7}, {%8,%9}, {%0,%1,%2,%3};"
        : "+f"(c[0]), "+f"(c[1]), "+f"(c[2]), "+f"(c[3])
        : "r"(a[0]), "r"(a[1]), "r"(a[2]), "r"(a[3]), "r"(b[0]), "r"(b[1]));
}
__device__ __forceinline__ void st2(float* p, float a, float b) { p[0] = a; p[1] = b; }
__device__ __forceinline__ void st2(__half* p, float a, float b) {
    *(__half2*)p = __floats2half2_rn(a, b);
}

// ---------------- LayerNorm: one block (128 threads) per row of 512 --------
__global__ void ln_kernel(const float* __restrict__ x, const float* __restrict__ g,
                          const float* __restrict__ bb, float* __restrict__ out) {
    const int row = blockIdx.x;
    const int tid = threadIdx.x;
    const float4* xr = (const float4*)(x + (size_t)row * DIM);
    float4 v = xr[tid];
    float s  = v.x + v.y + v.z + v.w;
    float ss = v.x*v.x + v.y*v.y + v.z*v.z + v.w*v.w;
    #pragma unroll
    for (int o = 16; o > 0; o >>= 1) {
        s  += __shfl_xor_sync(0xffffffffu, s,  o);
        ss += __shfl_xor_sync(0xffffffffu, ss, o);
    }
    __shared__ float as_[4], ass_[4];
    if ((tid & 31) == 0) { as_[tid >> 5] = s; ass_[tid >> 5] = ss; }
    __syncthreads();
    s  = as_[0] + as_[1] + as_[2] + as_[3];
    ss = ass_[0] + ass_[1] + ass_[2] + ass_[3];
    const float mean = s * (1.0f / DIM);
    const float var  = ss * (1.0f / DIM) - mean * mean;
    const float inv  = rsqrtf(var + 1e-5f);
    float4 gv = ((const float4*)g)[tid];
    float4 bv = ((const float4*)bb)[tid];
    float4 r;
    r.x = (v.x - mean) * inv * gv.x + bv.x;
    r.y = (v.y - mean) * inv * gv.y + bv.y;
    r.z = (v.z - mean) * inv * gv.z + bv.z;
    r.w = (v.w - mean) * inv * gv.w + bv.w;
    ((float4*)(out + (size_t)row * DIM))[tid] = r;
}

// ---------------- tf32 tensor-core GEMM (proven R2/R5), output type OT ------
#define LDK 36   // smem row stride in words (pad 32->36: conflict-free frags)

template <int EPI, typename OT>
__global__ __launch_bounds__(256)
void tgemm(const float* __restrict__ A, const float* __restrict__ W,
           const float* __restrict__ bias, const float* __restrict__ R,
           OT* __restrict__ C, int M, int N, int K) {
    __shared__ uint32_t As[128 * LDK];
    __shared__ uint32_t Bs[128 * LDK];

    const int tid  = threadIdx.x;
    const int warp = tid >> 5;
    const int lane = tid & 31;
    const int g    = lane >> 2;
    const int t4   = lane & 3;
    const int wm   = warp >> 2;
    const int wn   = warp & 3;

    const int bm = blockIdx.y * 128;
    const int bn = blockIdx.x * 128;

    const int lrow = tid >> 1;
    const int lkof = (tid & 1) * 16;

    const float* Ap = A + (size_t)(bm + lrow) * K + lkof;
    const float* Wp = W + (size_t)(bn + lrow) * K + lkof;
    uint32_t* dstA = As + lrow * LDK + lkof;
    uint32_t* dstB = Bs + lrow * LDK + lkof;

    float acc[4][4][4];
    #pragma unroll
    for (int i = 0; i < 4; i++)
        #pragma unroll
        for (int j = 0; j < 4; j++)
            #pragma unroll
            for (int v = 0; v < 4; v++) acc[i][j][v] = 0.0f;

    const uint32_t* afb = As + (wm * 64 + g) * LDK;
    const uint32_t* bfb = Bs + (wn * 32 + g) * LDK;

    for (int k0 = 0; k0 < K; k0 += 32) {
        float4 av[4], wv[4];
        #pragma unroll
        for (int i = 0; i < 4; i++) {
            av[i] = *(const float4*)(Ap + k0 + i * 4);
            wv[i] = *(const float4*)(Wp + k0 + i * 4);
        }
        __syncthreads();
        #pragma unroll
        for (int i = 0; i < 4; i++) {
            *(uint4*)(dstA + i * 4) = pack_tf32(av[i]);
            *(uint4*)(dstB + i * 4) = pack_tf32(wv[i]);
        }
        __syncthreads();

        #pragma unroll
        for (int kk = 0; kk < 32; kk += 8) {
            uint32_t af[4][4], bf[4][2];
            #pragma unroll
            for (int mt = 0; mt < 4; mt++) {
                const uint32_t* p = afb + mt * (16 * LDK) + kk + t4;
                af[mt][0] = p[0];
                af[mt][1] = p[8 * LDK];
                af[mt][2] = p[4];
                af[mt][3] = p[8 * LDK + 4];
            }
            #pragma unroll
            for (int nt = 0; nt < 4; nt++) {
                const uint32_t* p = bfb + nt * (8 * LDK) + kk + t4;
                bf[nt][0] = p[0];
                bf[nt][1] = p[4];
            }
            #pragma unroll
            for (int mt = 0; mt < 4; mt++)
                #pragma unroll
                for (int nt = 0; nt < 4; nt++)
                    mma_tf32(acc[mt][nt], af[mt], bf[nt]);
        }
    }

    #pragma unroll
    for (int mt = 0; mt < 4; mt++) {
        const int r0 = bm + wm * 64 + mt * 16 + g;
        const int r1 = r0 + 8;
        #pragma unroll
        for (int nt = 0; nt < 4; nt++) {
            const int col = bn + wn * 32 + nt * 8 + 2 * t4;
            const float b0 = bias[col], b1 = bias[col + 1];
            float v0 = acc[mt][nt][0] + b0;
            float v1 = acc[mt][nt][1] + b1;
            float v2 = acc[mt][nt][2] + b0;
            float v3 = acc[mt][nt][3] + b1;
            if (EPI == 1) {
                v0 = gelu_exact(v0); v1 = gelu_exact(v1);
                v2 = gelu_exact(v2); v3 = gelu_exact(v3);
            }
            if (EPI == 2) {
                v0 += R[(size_t)r0 * N + col];
                v1 += R[(size_t)r0 * N + col + 1];
                v2 += R[(size_t)r1 * N + col];
                v3 += R[(size_t)r1 * N + col + 1];
            }
            st2(C + (size_t)r0 * N + col, v0, v1);
            st2(C + (size_t)r1 * N + col, v2, v3);
        }
    }
}

// ---------------- Tiled local+global attention (fp16 tiles, fp32 softmax) ----
// Block = 32 queries x (h, b). Key slots: {0} U [q0-64, q0+31+64] (<=161).
// Scores via fp16 MMA; R5's per-query window mask applied in softmax.
#define TQ   32
#define NKP  168   // slot capacity (21 n-tiles of 8)
#define LDA  36    // words (half2) per 64-half row: 32 + 4 pad
#define SP   172   // score row stride (floats)
#define ATTN_SMEM ((32 * LDA + 2 * NKP * LDA) * 4 + 32 * SP * 4 + 176 + 128)

__global__ __launch_bounds__(256)
void attn_tile_kernel(const __half* __restrict__ qkv,
                      const unsigned char* __restrict__ pad,
                      float* __restrict__ o) {
    extern __shared__ __align__(16) uint32_t sm[];
    uint32_t* Qs  = sm;                        // 32*LDA   (half2 words)
    uint32_t* Ksm = Qs + 32 * LDA;             // NKP*LDA
    uint32_t* Vsm = Ksm + NKP * LDA;           // NKP*LDA
    float*    Sf  = (float*)(Vsm + NKP * LDA); // 32*SP
    unsigned char* pads = (unsigned char*)(Sf + 32 * SP);  // 176 B
    float*    invs = (float*)(pads + 176);     // 32 floats

    const int q0 = blockIdx.x * TQ;
    const int h  = blockIdx.y;
    const int b  = blockIdx.z;
    const int tid  = threadIdx.x;
    const int warp = tid >> 5;
    const int lane = tid & 31;
    const int g    = lane >> 2;
    const int t4   = lane & 3;

    int ks = q0 - WIN; if (ks < 0) ks = 0;
    int ke = q0 + TQ - 1 + WIN; if (ke > SQ - 1) ke = SQ - 1;
    const int hasg = (ks > 0) ? 1 : 0;
    const int nk = ke - ks + 1 + hasg;           // <= 161
    const int ntmax = (nk + 7) >> 3;

    // ---- load Q tile (32 x 64 halves): 8 threads per row, uint4 (8 halves)
    {
        const int qrow = tid >> 3, l8 = tid & 7;
        const __half* src = qkv + ((size_t)(b * SQ + q0 + qrow)) * QKVD
                            + h * HDIM + l8 * 8;
        *(uint4*)(Qs + qrow * LDA + l8 * 4) = *(const uint4*)src;
    }
    // ---- load K/V slots + pad flags ----
    {
        const int l8 = tid & 7;
        for (int j = tid >> 3; j < nk; j += 32) {
            const int kj = (hasg && j == 0) ? 0 : ks + j - hasg;
            const __half* base = qkv + ((size_t)(b * SQ + kj)) * QKVD;
            *(uint4*)(Ksm + j * LDA + l8 * 4) =
                *(const uint4*)(base + DIM + h * HDIM + l8 * 8);
            *(uint4*)(Vsm + j * LDA + l8 * 4) =
                *(const uint4*)(base + 2 * DIM + h * HDIM + l8 * 8);
            if (l8 == 0) pads[j] = pad[b * SQ + kj];
        }
    }
    __syncthreads();

    // ---- scores S[32][nk] = Q @ K^T (fp16 MMA, fp32 accum) ----
    {
        const int mt = warp & 1;          // m-tile of 16
        const int ng = warp >> 1;         // n-tile group 0..3
        const int l15 = lane & 15;
        const uint32_t aAddr = smem_u32(Qs) +
            (((mt * 16 + l15) * LDA) + (lane >> 4) * 4) * 4;
        uint32_t af[4][4];
        #pragma unroll
        for (int kk = 0; kk < 4; kk++) ldsm_x4(af[kk], aAddr + kk * 32);

        const uint32_t bAddr = smem_u32(Ksm) +
            (((l15 & 7) * LDA) + (l15 >> 3) * 4) * 4;
        for (int nt = ng; nt < ntmax; nt += 4) {
            float c[4] = {0.f, 0.f, 0.f, 0.f};
            #pragma unroll
            for (int kk = 0; kk < 4; kk++) {
                uint32_t bf[2];
                ldsm_x2(bf, bAddr + nt * (8 * LDA * 4) + kk * 32);
                mma16816(c, af[kk], bf);
            }
            const int r0 = mt * 16 + g;
            const int col = nt * 8 + 2 * t4;
            Sf[r0 * SP + col]           = c[0];
            Sf[r0 * SP + col + 1]       = c[1];
            Sf[(r0 + 8) * SP + col]     = c[2];
            Sf[(r0 + 8) * SP + col + 1] = c[3];
        }
    }
    __syncthreads();

    // ---- softmax rows (8 threads per query) with per-query window mask ----
    {
        const int q = tid >> 3, sub = tid & 7;
        const int qg = q0 + q;
        float* Sr = Sf + q * SP;
        float mx = -1e30f;
        for (int j = sub; j < nk; j += 8) {
            const int kj = (hasg && j == 0) ? 0 : ks + j - hasg;
            float s = Sr[j] * 0.125f;
            const int d = kj - qg;
            const bool valid = (kj == 0) || (d >= -WIN && d <= WIN);
            if (!valid || pads[j]) s = -1e30f;
            Sr[j] = s;
            mx = fmaxf(mx, s);
        }
        #pragma unroll
        for (int off = 4; off > 0; off >>= 1)
            mx = fmaxf(mx, __shfl_xor_sync(0xffffffffu, mx, off, 8));
        float sum = 0.f;
        for (int j = sub; j < nk; j += 8) {
            float e = expf(Sr[j] - mx);
            Sr[j] = e;
            sum += e;
        }
        #pragma unroll
        for (int off = 4; off > 0; off >>= 1)
            sum += __shfl_xor_sync(0xffffffffu, sum, off, 8);
        if (sub == 0) invs[q] = 1.0f / sum;
    }
    __syncthreads();

    // ---- P @ V : thread = (q, 8-dim group); V read as half2 ----
    {
        const int q = tid >> 3, dg = tid & 7;
        float a0=0,a1=0,a2=0,a3=0,a4=0,a5=0,a6=0,a7=0;
        const float* Sr = Sf + q * SP;
        const uint32_t* Vb = Vsm + dg * 4;
        for (int j = 0; j < nk; j++) {
            const float p = Sr[j];
            uint4 v = *(const uint4*)(Vb + j * LDA);
            float2 f0 = __half22float2(*(__half2*)&v.x);
            float2 f1 = __half22float2(*(__half2*)&v.y);
            float2 f2 = __half22float2(*(__half2*)&v.z);
            float2 f3 = __half22float2(*(__half2*)&v.w);
            a0 += p * f0.x; a1 += p * f0.y; a2 += p * f1.x; a3 += p * f1.y;
            a4 += p * f2.x; a5 += p * f2.y; a6 += p * f3.x; a7 += p * f3.y;
        }
        const float inv = invs[q];
        float* op = o + ((size_t)(b * SQ + q0 + q)) * DIM + h * HDIM + dg * 8;
        float4 r0 = { a0 * inv, a1 * inv, a2 * inv, a3 * inv };
        float4 r1 = { a4 * inv, a5 * inv, a6 * inv, a7 * inv };
        *(float4*)op = r0;
        *(float4*)(op + 4) = r1;
    }
}

// ---------------- query-0 global attention: split-softmax --------------------
// Pass 1: grid (NH, NB, 8); each block does 256 keys -> partial (m, s, acc).
__global__ __launch_bounds__(256)
void attn_g1_kernel(const __half* __restrict__ qkv,
                    const unsigned char* __restrict__ pad,
                    float* __restrict__ pm, float* __restrict__ ps,
                    float* __restrict__ pa) {
    const int h = blockIdx.x, b = blockIdx.y, c = blockIdx.z;
    const int tid = threadIdx.x;
    const int idx = (b * NH + h) * 8 + c;
    __shared__ float qf[HDIM];
    __shared__ float S2[256];
    __shared__ float red[256];

    if (tid < HDIM)
        qf[tid] = __half2float(qkv[((size_t)(b * SQ)) * QKVD + h * HDIM + tid]);
    __syncthreads();

    const int j = c * 256 + tid;
    {
        const __half2* kp = (const __half2*)(qkv + ((size_t)(b * SQ + j)) * QKVD
                                             + DIM + h * HDIM);
        float s = 0.f;
        #pragma unroll
        for (int i = 0; i < 32; i++) {
            float2 f = __half22float2(kp[i]);
            s += qf[2 * i] * f.x + qf[2 * i + 1] * f.y;
        }
        s *= 0.125f;
        if (pad[b * SQ + j]) s = -1e30f;
        S2[tid] = s;
        red[tid] = s;
    }
    __syncthreads();
    for (int st = 128; st > 0; st >>= 1) {
        if (tid < st) red[tid] = fmaxf(red[tid], red[tid + st]);
        __syncthreads();
    }
    const float mx = red[0];
    __syncthreads();
    {
        float e = expf(S2[tid] - mx);
        S2[tid] = e;
        red[tid] = e;
    }
    __syncthreads();
    for (int st = 128; st > 0; st >>= 1) {
        if (tid < st) red[tid] += red[tid + st];
        __syncthreads();
    }
    if (tid == 0) { pm[idx] = mx; ps[idx] = red[0]; }
    __syncthreads();

    // partial P@V over this chunk
    const int d = tid & 63, grp = tid >> 6;
    float acc = 0.f;
    for (int t = grp; t < 256; t += 4)
        acc += S2[t] * __half2float(qkv[((size_t)(b * SQ + c * 256 + t)) * QKVD
                                        + 2 * DIM + h * HDIM + d]);
    red[tid] = acc;
    __syncthreads();
    if (tid < HDIM)
        pa[(size_t)idx * HDIM + tid] =
            red[tid] + red[tid + 64] + red[tid + 128] + red[tid + 192];
}

// Pass 2: grid (NH, NB), 64 threads; combine 8 partials, overwrite o row 0.
__global__ __launch_bounds__(64)
void attn_g2_kernel(const float* __restrict__ pm, const float* __restrict__ ps,
                    const float* __restrict__ pa, float* __restrict__ o) {
    const int h = blockIdx.x, b = blockIdx.y;
    const int d = threadIdx.x;
    const int base = (b * NH + h) * 8;
    float M = -1e30f;
    #pragma unroll
    for (int c = 0; c < 8; c++) M = fmaxf(M, pm[base + c]);
    float S = 0.f, acc = 0.f;
    #pragma unroll
    for (int c = 0; c < 8; c++) {
        const float w = expf(pm[base + c] - M);
        S   += ps[base + c] * w;
        acc += pa[(size_t)(base + c) * HDIM + d] * w;
    }
    o[((size_t)(b * SQ)) * DIM + h * HDIM + d] = acc / S;
}

// ---------------- launch -----------------------------------------------------
extern "C" void kernel_launch(void* const* d_in, const int* in_sizes, int n_in,
                              void* d_out, int out_size) {
    const float* x   = (const float*)d_in[0];
    const unsigned char* pad = (const unsigned char*)d_in[1];
    const float* ipw = (const float*)d_in[3];
    const float* ipb = (const float*)d_in[4];
    const float* opw = (const float*)d_in[5];
    const float* opb = (const float*)d_in[6];
    const float* l1g = (const float*)d_in[7];
    const float* l1b = (const float*)d_in[8];
    const float* l2g = (const float*)d_in[9];
    const float* l2b = (const float*)d_in[10];
    const float* w1  = (const float*)d_in[11];
    const float* b1  = (const float*)d_in[12];
    const float* w2  = (const float*)d_in[13];
    const float* b2  = (const float*)d_in[14];
    float* out = (float*)d_out;

    float *a, *o, *x1, *f, *hh, *pm, *ps, *pa;
    __half* qkvh;
    cudaGetSymbolAddress((void**)&a,    g_a);
    cudaGetSymbolAddress((void**)&qkvh, g_qkvh);
    cudaGetSymbolAddress((void**)&o,    g_o);
    cudaGetSymbolAddress((void**)&x1,   g_x1);
    cudaGetSymbolAddress((void**)&f,    g_f);
    cudaGetSymbolAddress((void**)&hh,   g_h);
    cudaGetSymbolAddress((void**)&pm,   g_pm);
    cudaGetSymbolAddress((void**)&ps,   g_ps);
    cudaGetSymbolAddress((void**)&pa,   g_pa);

    cudaFuncSetAttribute(attn_tile_kernel,
                         cudaFuncAttributeMaxDynamicSharedMemorySize, ATTN_SMEM);

    // 1. pre-LN for attention
    ln_kernel<<<MROWS, 128>>>(x, l1g, l1b, a);
    // 2. QKV projection -> half
    tgemm<0, __half><<<dim3(QKVD / 128, MROWS / 128), 256>>>(a, ipw, ipb, nullptr,
                                                             qkvh, MROWS, QKVD, DIM);
    // 3. attention: tiled local windows, then q==0 global split-softmax fix-up
    attn_tile_kernel<<<dim3(SQ / TQ, NH, NB), 256, ATTN_SMEM>>>(qkvh, pad, o);
    attn_g1_kernel<<<dim3(NH, NB, 8), 256>>>(qkvh, pad, pm, ps, pa);
    attn_g2_kernel<<<dim3(NH, NB), 64>>>(pm, ps, pa, o);
    // 4. out projection + residual -> x1
    tgemm<2, float><<<dim3(DIM / 128, MROWS / 128), 256>>>(o, opw, opb, x, x1,
                                                           MROWS, DIM, DIM);
    // 5. pre-LN for FF
    ln_kernel<<<MROWS, 128>>>(x1, l2g, l2b, f);
    // 6. FF1 + exact GELU
    tgemm<1, float><<<dim3(FFD / 128, MROWS / 128), 256>>>(f, w1, b1, nullptr, hh,
                                                           MROWS, FFD, DIM);
    // 7. FF2 + residual -> final output
    tgemm<2, float><<<dim3(DIM / 128, MROWS / 128), 256>>>(hh, w2, b2, x1, out,
                                                           MROWS, DIM, FFD);
}

// round 7
// speedup vs baseline: 5.9632x; 1.6319x over previous
#include <cuda_runtime.h>
#include <cuda_fp16.h>
#include <math.h>
#include <stdint.h>

#define SQ   2048
#define DIM  512
#define NH   8
#define HDIM 64
#define NB   4
#define WIN  64
#define MROWS (NB * SQ)        // 8192
#define QKVD (3 * DIM)         // 1536
#define FFD  2048

// ---------------- scratch ----------------------------------------------------
__device__ __half g_a   [(size_t)MROWS * DIM];
__device__ __half g_qkvh[(size_t)MROWS * QKVD];
__device__ __half g_o   [(size_t)MROWS * DIM];
__device__ float  g_x1  [(size_t)MROWS * DIM];
__device__ __half g_f   [(size_t)MROWS * DIM];
__device__ __half g_h   [(size_t)MROWS * FFD];
__device__ __half g_wqkv[(size_t)QKVD * DIM];
__device__ __half g_wo  [(size_t)DIM * DIM];
__device__ __half g_w1h [(size_t)FFD * DIM];
__device__ __half g_w2h [(size_t)DIM * FFD];
// split-softmax partials for query-0 global attention
__device__ float  g_pm  [NB * NH * 8];
__device__ float  g_ps  [NB * NH * 8];
__device__ float  g_pa  [NB * NH * 8 * HDIM];

// ---------------- helpers ----------------------------------------------------
__device__ __forceinline__ uint32_t smem_u32(const void* p) {
    return (uint32_t)__cvta_generic_to_shared(p);
}
__device__ __forceinline__ void ldsm_x4(uint32_t* r, uint32_t addr) {
    asm volatile("ldmatrix.sync.aligned.m8n8.x4.shared.b16 {%0,%1,%2,%3}, [%4];\n"
        : "=r"(r[0]), "=r"(r[1]), "=r"(r[2]), "=r"(r[3]) : "r"(addr));
}
__device__ __forceinline__ void ldsm_x2(uint32_t* r, uint32_t addr) {
    asm volatile("ldmatrix.sync.aligned.m8n8.x2.shared.b16 {%0,%1}, [%2];\n"
        : "=r"(r[0]), "=r"(r[1]) : "r"(addr));
}
__device__ __forceinline__ void mma16816(float* c, const uint32_t* a, const uint32_t* b) {
    asm volatile(
        "mma.sync.aligned.m16n8k16.row.col.f32.f16.f16.f32 "
        "{%0,%1,%2,%3},{%4,%5,%6,%7},{%8,%9},{%0,%1,%2,%3};\n"
        : "+f"(c[0]), "+f"(c[1]), "+f"(c[2]), "+f"(c[3])
        : "r"(a[0]), "r"(a[1]), "r"(a[2]), "r"(a[3]), "r"(b[0]), "r"(b[1]));
}
__device__ __forceinline__ void cp16(uint32_t saddr, const void* g) {
    asm volatile("cp.async.ca.shared.global [%0], [%1], 16;\n" :: "r"(saddr), "l"(g));
}
#define CP_COMMIT() asm volatile("cp.async.commit_group;\n" ::: "memory")
#define CP_WAIT0()  asm volatile("cp.async.wait_group 0;\n" ::: "memory")

__device__ __forceinline__ float gelu_exact(float v) {
    return 0.5f * v * (1.0f + erff(v * 0.70710678118654752f));
}
__device__ __forceinline__ void st2(float* p, float a, float b) { p[0] = a; p[1] = b; }
__device__ __forceinline__ void st2(__half* p, float a, float b) {
    *(__half2*)p = __floats2half2_rn(a, b);
}

// ---------------- fp32 -> fp16 convert --------------------------------------
__global__ void f2h_kernel(const float* __restrict__ s, __half* __restrict__ d, int n) {
    int i = (blockIdx.x * blockDim.x + threadIdx.x) * 4;
    if (i < n) {
        float4 v = *(const float4*)(s + i);
        ((__half2*)d)[i / 2]     = __floats2half2_rn(v.x, v.y);
        ((__half2*)d)[i / 2 + 1] = __floats2half2_rn(v.z, v.w);
    }
}

// ---------------- LayerNorm: float in, half out ------------------------------
__global__ void ln_kernel(const float* __restrict__ x, const float* __restrict__ g,
                          const float* __restrict__ bb, __half* __restrict__ out) {
    const int row = blockIdx.x;
    const int tid = threadIdx.x;
    const float4* xr = (const float4*)(x + (size_t)row * DIM);
    float4 v = xr[tid];
    float s  = v.x + v.y + v.z + v.w;
    float ss = v.x*v.x + v.y*v.y + v.z*v.z + v.w*v.w;
    #pragma unroll
    for (int o = 16; o > 0; o >>= 1) {
        s  += __shfl_xor_sync(0xffffffffu, s,  o);
        ss += __shfl_xor_sync(0xffffffffu, ss, o);
    }
    __shared__ float as_[4], ass_[4];
    if ((tid & 31) == 0) { as_[tid >> 5] = s; ass_[tid >> 5] = ss; }
    __syncthreads();
    s  = as_[0] + as_[1] + as_[2] + as_[3];
    ss = ass_[0] + ass_[1] + ass_[2] + ass_[3];
    const float mean = s * (1.0f / DIM);
    const float var  = ss * (1.0f / DIM) - mean * mean;
    const float inv  = rsqrtf(var + 1e-5f);
    float4 gv = ((const float4*)g)[tid];
    float4 bv = ((const float4*)bb)[tid];
    float r0 = (v.x - mean) * inv * gv.x + bv.x;
    float r1 = (v.y - mean) * inv * gv.y + bv.y;
    float r2 = (v.z - mean) * inv * gv.z + bv.z;
    float r3 = (v.w - mean) * inv * gv.w + bv.w;
    __half2* orow = (__half2*)(out + (size_t)row * DIM);
    orow[2 * tid]     = __floats2half2_rn(r0, r1);
    orow[2 * tid + 1] = __floats2half2_rn(r2, r3);
}

// ---------------- fp16 tensor-core GEMM (pipelined, validated in R3) ---------
// C[M,N] = A[M,K] @ W[N,K]^T (+bias, epilogue). A,W half; C = OT.
// EPI: 0 = bias, 1 = bias+GELU, 2 = bias+residual(float R)
#define LDK 20           // smem words (half2) per 32-half row (16 + pad 4)
#define STGW (128 * LDK) // words per stage

template <int EPI, typename OT>
__global__ __launch_bounds__(256)
void tgemm(const __half* __restrict__ A, const __half* __restrict__ W,
           const float* __restrict__ bias, const float* __restrict__ R,
           OT* __restrict__ C, int M, int N, int K) {
    __shared__ __align__(16) uint32_t As[2 * STGW];
    __shared__ __align__(16) uint32_t Bs[2 * STGW];

    const int tid  = threadIdx.x;
    const int warp = tid >> 5;
    const int lane = tid & 31;
    const int g    = lane >> 2;
    const int t4   = lane & 3;
    const int wm   = warp >> 2;   // 0..1 -> 64 rows
    const int wn   = warp & 3;    // 0..3 -> 32 cols

    const int bm = blockIdx.y * 128;
    const int bn = blockIdx.x * 128;

    // cp.async loaders: 2 threads/row, 16 halves (32B) each
    const int lrow = tid >> 1;
    const __half* gA = A + (size_t)(bm + lrow) * K + (tid & 1) * 16;
    const __half* gB = W + (size_t)(bn + lrow) * K + (tid & 1) * 16;
    const uint32_t sA = smem_u32(As) + (lrow * LDK + (tid & 1) * 8) * 4;
    const uint32_t sB = smem_u32(Bs) + (lrow * LDK + (tid & 1) * 8) * 4;
    const int STGB = STGW * 4;

    // ldmatrix base addresses (stage 0, kk 0)
    const int l15 = lane & 15;
    const uint32_t aBase = smem_u32(As) +
        (((wm * 64 + l15) * LDK) + (lane >> 4) * 4) * 4;
    const uint32_t bBase = smem_u32(Bs) +
        (((wn * 32 + (l15 & 7)) * LDK) + ((l15 >> 3) * 4)) * 4;

    float acc[4][4][4];
    #pragma unroll
    for (int i = 0; i < 4; i++)
        #pragma unroll
        for (int j = 0; j < 4; j++)
            #pragma unroll
            for (int v = 0; v < 4; v++) acc[i][j][v] = 0.0f;

    const int NT = K / 32;
    // prologue load
    cp16(sA, gA); cp16(sA + 16, gA + 8);
    cp16(sB, gB); cp16(sB + 16, gB + 8);
    CP_COMMIT();

    for (int t = 0; t < NT; t++) {
        CP_WAIT0();
        __syncthreads();
        if (t + 1 < NT) {
            const int s = (t + 1) & 1;
            const int k0 = (t + 1) * 32;
            cp16(sA + s * STGB, gA + k0); cp16(sA + s * STGB + 16, gA + k0 + 8);
            cp16(sB + s * STGB, gB + k0); cp16(sB + s * STGB + 16, gB + k0 + 8);
            CP_COMMIT();
        }
        const int sb = (t & 1) * STGB;
        #pragma unroll
        for (int kk = 0; kk < 2; kk++) {
            uint32_t af[4][4], bf[4][2];
            #pragma unroll
            for (int mt = 0; mt < 4; mt++)
                ldsm_x4(af[mt], aBase + sb + mt * (16 * LDK * 4) + kk * 32);
            #pragma unroll
            for (int nt = 0; nt < 4; nt++)
                ldsm_x2(bf[nt], bBase + sb + nt * (8 * LDK * 4) + kk * 32);
            #pragma unroll
            for (int mt = 0; mt < 4; mt++)
                #pragma unroll
                for (int nt = 0; nt < 4; nt++)
                    mma16816(acc[mt][nt], af[mt], bf[nt]);
        }
        __syncthreads();
    }

    // epilogue
    #pragma unroll
    for (int mt = 0; mt < 4; mt++) {
        const int r0 = bm + wm * 64 + mt * 16 + g;
        const int r1 = r0 + 8;
        #pragma unroll
        for (int nt = 0; nt < 4; nt++) {
            const int col = bn + wn * 32 + nt * 8 + 2 * t4;
            const float b0 = bias[col], b1 = bias[col + 1];
            float v0 = acc[mt][nt][0] + b0;
            float v1 = acc[mt][nt][1] + b1;
            float v2 = acc[mt][nt][2] + b0;
            float v3 = acc[mt][nt][3] + b1;
            if (EPI == 1) {
                v0 = gelu_exact(v0); v1 = gelu_exact(v1);
                v2 = gelu_exact(v2); v3 = gelu_exact(v3);
            }
            if (EPI == 2) {
                v0 += R[(size_t)r0 * N + col];
                v1 += R[(size_t)r0 * N + col + 1];
                v2 += R[(size_t)r1 * N + col];
                v3 += R[(size_t)r1 * N + col + 1];
            }
            st2(C + (size_t)r0 * N + col, v0, v1);
            st2(C + (size_t)r1 * N + col, v2, v3);
        }
    }
}

// ---------------- Tiled local+global attention (fp16 tiles, fp32 softmax) ----
// Block = 32 queries x (h, b). Key slots: {0} U [q0-64, q0+31+64] (<=161).
// Scores via fp16 MMA; per-query window mask applied in softmax (proven R5/R6).
#define TQ   32
#define NKP  168   // slot capacity (21 n-tiles of 8)
#define LDA  36    // words (half2) per 64-half row: 32 + 4 pad
#define SP   172   // score row stride (floats)
#define ATTN_SMEM ((32 * LDA + 2 * NKP * LDA) * 4 + 32 * SP * 4 + 176 + 128)

__global__ __launch_bounds__(256)
void attn_tile_kernel(const __half* __restrict__ qkv,
                      const unsigned char* __restrict__ pad,
                      __half* __restrict__ o) {
    extern __shared__ __align__(16) uint32_t sm[];
    uint32_t* Qs  = sm;                        // 32*LDA
    uint32_t* Ksm = Qs + 32 * LDA;             // NKP*LDA
    uint32_t* Vsm = Ksm + NKP * LDA;           // NKP*LDA
    float*    Sf  = (float*)(Vsm + NKP * LDA); // 32*SP
    unsigned char* pads = (unsigned char*)(Sf + 32 * SP);  // 176 B
    float*    invs = (float*)(pads + 176);     // 32 floats

    const int q0 = blockIdx.x * TQ;
    const int h  = blockIdx.y;
    const int b  = blockIdx.z;
    const int tid  = threadIdx.x;
    const int warp = tid >> 5;
    const int lane = tid & 31;
    const int g    = lane >> 2;
    const int t4   = lane & 3;

    int ks = q0 - WIN; if (ks < 0) ks = 0;
    int ke = q0 + TQ - 1 + WIN; if (ke > SQ - 1) ke = SQ - 1;
    const int hasg = (ks > 0) ? 1 : 0;
    const int nk = ke - ks + 1 + hasg;           // <= 161
    const int ntmax = (nk + 7) >> 3;

    // ---- load Q tile (32 x 64 halves): 8 threads per row, uint4 (8 halves)
    {
        const int qrow = tid >> 3, l8 = tid & 7;
        const __half* src = qkv + ((size_t)(b * SQ + q0 + qrow)) * QKVD
                            + h * HDIM + l8 * 8;
        *(uint4*)(Qs + qrow * LDA + l8 * 4) = *(const uint4*)src;
    }
    // ---- load K/V slots + pad flags ----
    {
        const int l8 = tid & 7;
        for (int j = tid >> 3; j < nk; j += 32) {
            const int kj = (hasg && j == 0) ? 0 : ks + j - hasg;
            const __half* base = qkv + ((size_t)(b * SQ + kj)) * QKVD;
            *(uint4*)(Ksm + j * LDA + l8 * 4) =
                *(const uint4*)(base + DIM + h * HDIM + l8 * 8);
            *(uint4*)(Vsm + j * LDA + l8 * 4) =
                *(const uint4*)(base + 2 * DIM + h * HDIM + l8 * 8);
            if (l8 == 0) pads[j] = pad[b * SQ + kj];
        }
    }
    __syncthreads();

    // ---- scores S[32][nk] = Q @ K^T (fp16 MMA, fp32 accum) ----
    {
        const int mt = warp & 1;
        const int ng = warp >> 1;
        const int l15 = lane & 15;
        const uint32_t aAddr = smem_u32(Qs) +
            (((mt * 16 + l15) * LDA) + (lane >> 4) * 4) * 4;
        uint32_t af[4][4];
        #pragma unroll
        for (int kk = 0; kk < 4; kk++) ldsm_x4(af[kk], aAddr + kk * 32);

        const uint32_t bAddr = smem_u32(Ksm) +
            (((l15 & 7) * LDA) + (l15 >> 3) * 4) * 4;
        for (int nt = ng; nt < ntmax; nt += 4) {
            float c[4] = {0.f, 0.f, 0.f, 0.f};
            #pragma unroll
            for (int kk = 0; kk < 4; kk++) {
                uint32_t bf[2];
                ldsm_x2(bf, bAddr + nt * (8 * LDA * 4) + kk * 32);
                mma16816(c, af[kk], bf);
            }
            const int r0 = mt * 16 + g;
            const int col = nt * 8 + 2 * t4;
            Sf[r0 * SP + col]           = c[0];
            Sf[r0 * SP + col + 1]       = c[1];
            Sf[(r0 + 8) * SP + col]     = c[2];
            Sf[(r0 + 8) * SP + col + 1] = c[3];
        }
    }
    __syncthreads();

    // ---- softmax rows (8 threads per query) with per-query window mask ----
    {
        const int q = tid >> 3, sub = tid & 7;
        const int qg = q0 + q;
        float* Sr = Sf + q * SP;
        float mx = -1e30f;
        for (int j = sub; j < nk; j += 8) {
            const int kj = (hasg && j == 0) ? 0 : ks + j - hasg;
            float s = Sr[j] * 0.125f;
            const int d = kj - qg;
            const bool valid = (kj == 0) || (d >= -WIN && d <= WIN);
            if (!valid || pads[j]) s = -1e30f;
            Sr[j] = s;
            mx = fmaxf(mx, s);
        }
        #pragma unroll
        for (int off = 4; off > 0; off >>= 1)
            mx = fmaxf(mx, __shfl_xor_sync(0xffffffffu, mx, off, 8));
        float sum = 0.f;
        for (int j = sub; j < nk; j += 8) {
            float e = expf(Sr[j] - mx);
            Sr[j] = e;
            sum += e;
        }
        #pragma unroll
        for (int off = 4; off > 0; off >>= 1)
            sum += __shfl_xor_sync(0xffffffffu, sum, off, 8);
        if (sub == 0) invs[q] = 1.0f / sum;
    }
    __syncthreads();

    // ---- P @ V : thread = (q, 8-dim group); V read as half2; out half -----
    {
        const int q = tid >> 3, dg = tid & 7;
        float a0=0,a1=0,a2=0,a3=0,a4=0,a5=0,a6=0,a7=0;
        const float* Sr = Sf + q * SP;
        const uint32_t* Vb = Vsm + dg * 4;
        for (int j = 0; j < nk; j++) {
            const float p = Sr[j];
            uint4 v = *(const uint4*)(Vb + j * LDA);
            float2 f0 = __half22float2(*(__half2*)&v.x);
            float2 f1 = __half22float2(*(__half2*)&v.y);
            float2 f2 = __half22float2(*(__half2*)&v.z);
            float2 f3 = __half22float2(*(__half2*)&v.w);
            a0 += p * f0.x; a1 += p * f0.y; a2 += p * f1.x; a3 += p * f1.y;
            a4 += p * f2.x; a5 += p * f2.y; a6 += p * f3.x; a7 += p * f3.y;
        }
        const float inv = invs[q];
        __half2 h0 = __floats2half2_rn(a0 * inv, a1 * inv);
        __half2 h1 = __floats2half2_rn(a2 * inv, a3 * inv);
        __half2 h2 = __floats2half2_rn(a4 * inv, a5 * inv);
        __half2 h3 = __floats2half2_rn(a6 * inv, a7 * inv);
        uint4 u;
        u.x = *(uint32_t*)&h0; u.y = *(uint32_t*)&h1;
        u.z = *(uint32_t*)&h2; u.w = *(uint32_t*)&h3;
        *(uint4*)(o + ((size_t)(b * SQ + q0 + q)) * DIM + h * HDIM + dg * 8) = u;
    }
}

// ---------------- query-0 global attention: split-softmax --------------------
__global__ __launch_bounds__(256)
void attn_g1_kernel(const __half* __restrict__ qkv,
                    const unsigned char* __restrict__ pad,
                    float* __restrict__ pm, float* __restrict__ ps,
                    float* __restrict__ pa) {
    const int h = blockIdx.x, b = blockIdx.y, c = blockIdx.z;
    const int tid = threadIdx.x;
    const int idx = (b * NH + h) * 8 + c;
    __shared__ float qf[HDIM];
    __shared__ float S2[256];
    __shared__ float red[256];

    if (tid < HDIM)
        qf[tid] = __half2float(qkv[((size_t)(b * SQ)) * QKVD + h * HDIM + tid]);
    __syncthreads();

    const int j = c * 256 + tid;
    {
        const __half2* kp = (const __half2*)(qkv + ((size_t)(b * SQ + j)) * QKVD
                                             + DIM + h * HDIM);
        float s = 0.f;
        #pragma unroll
        for (int i = 0; i < 32; i++) {
            float2 f = __half22float2(kp[i]);
            s += qf[2 * i] * f.x + qf[2 * i + 1] * f.y;
        }
        s *= 0.125f;
        if (pad[b * SQ + j]) s = -1e30f;
        S2[tid] = s;
        red[tid] = s;
    }
    __syncthreads();
    for (int st = 128; st > 0; st >>= 1) {
        if (tid < st) red[tid] = fmaxf(red[tid], red[tid + st]);
        __syncthreads();
    }
    const float mx = red[0];
    __syncthreads();
    {
        float e = expf(S2[tid] - mx);
        S2[tid] = e;
        red[tid] = e;
    }
    __syncthreads();
    for (int st = 128; st > 0; st >>= 1) {
        if (tid < st) red[tid] += red[tid + st];
        __syncthreads();
    }
    if (tid == 0) { pm[idx] = mx; ps[idx] = red[0]; }
    __syncthreads();

    const int d = tid & 63, grp = tid >> 6;
    float acc = 0.f;
    for (int t = grp; t < 256; t += 4)
        acc += S2[t] * __half2float(qkv[((size_t)(b * SQ + c * 256 + t)) * QKVD
                                        + 2 * DIM + h * HDIM + d]);
    red[tid] = acc;
    __syncthreads();
    if (tid < HDIM)
        pa[(size_t)idx * HDIM + tid] =
            red[tid] + red[tid + 64] + red[tid + 128] + red[tid + 192];
}

__global__ __launch_bounds__(64)
void attn_g2_kernel(const float* __restrict__ pm, const float* __restrict__ ps,
                    const float* __restrict__ pa, __half* __restrict__ o) {
    const int h = blockIdx.x, b = blockIdx.y;
    const int d = threadIdx.x;
    const int base = (b * NH + h) * 8;
    float M = -1e30f;
    #pragma unroll
    for (int c = 0; c < 8; c++) M = fmaxf(M, pm[base + c]);
    float S = 0.f, acc = 0.f;
    #pragma unroll
    for (int c = 0; c < 8; c++) {
        const float w = expf(pm[base + c] - M);
        S   += ps[base + c] * w;
        acc += pa[(size_t)(base + c) * HDIM + d] * w;
    }
    o[((size_t)(b * SQ)) * DIM + h * HDIM + d] = __float2half(acc / S);
}

// ---------------- launch -----------------------------------------------------
extern "C" void kernel_launch(void* const* d_in, const int* in_sizes, int n_in,
                              void* d_out, int out_size) {
    const float* x   = (const float*)d_in[0];
    const unsigned char* pad = (const unsigned char*)d_in[1];
    const float* ipw = (const float*)d_in[3];
    const float* ipb = (const float*)d_in[4];
    const float* opw = (const float*)d_in[5];
    const float* opb = (const float*)d_in[6];
    const float* l1g = (const float*)d_in[7];
    const float* l1b = (const float*)d_in[8];
    const float* l2g = (const float*)d_in[9];
    const float* l2b = (const float*)d_in[10];
    const float* w1  = (const float*)d_in[11];
    const float* b1  = (const float*)d_in[12];
    const float* w2  = (const float*)d_in[13];
    const float* b2  = (const float*)d_in[14];
    float* out = (float*)d_out;

    __half *a, *qkvh, *o, *f, *hh, *wqkv, *wo, *w1h, *w2h;
    float *x1, *pm, *ps, *pa;
    cudaGetSymbolAddress((void**)&a,    g_a);
    cudaGetSymbolAddress((void**)&qkvh, g_qkvh);
    cudaGetSymbolAddress((void**)&o,    g_o);
    cudaGetSymbolAddress((void**)&x1,   g_x1);
    cudaGetSymbolAddress((void**)&f,    g_f);
    cudaGetSymbolAddress((void**)&hh,   g_h);
    cudaGetSymbolAddress((void**)&wqkv, g_wqkv);
    cudaGetSymbolAddress((void**)&wo,   g_wo);
    cudaGetSymbolAddress((void**)&w1h,  g_w1h);
    cudaGetSymbolAddress((void**)&w2h,  g_w2h);
    cudaGetSymbolAddress((void**)&pm,   g_pm);
    cudaGetSymbolAddress((void**)&ps,   g_ps);
    cudaGetSymbolAddress((void**)&pa,   g_pa);

    cudaFuncSetAttribute(attn_tile_kernel,
                         cudaFuncAttributeMaxDynamicSharedMemorySize, ATTN_SMEM);

    // weight conversions (once per call; graph-capturable)
    f2h_kernel<<<(QKVD * DIM / 4 + 255) / 256, 256>>>(ipw, wqkv, QKVD * DIM);
    f2h_kernel<<<(DIM * DIM / 4 + 255) / 256, 256>>>(opw, wo, DIM * DIM);
    f2h_kernel<<<(FFD * DIM / 4 + 255) / 256, 256>>>(w1, w1h, FFD * DIM);
    f2h_kernel<<<(DIM * FFD / 4 + 255) / 256, 256>>>(w2, w2h, DIM * FFD);

    // 1. pre-LN for attention -> half
    ln_kernel<<<MROWS, 128>>>(x, l1g, l1b, a);
    // 2. QKV projection (fp16 MMA) -> half
    tgemm<0, __half><<<dim3(QKVD / 128, MROWS / 128), 256>>>(a, wqkv, ipb, nullptr,
                                                             qkvh, MROWS, QKVD, DIM);
    // 3. attention: tiled local windows + q==0 global split-softmax fix-up
    attn_tile_kernel<<<dim3(SQ / TQ, NH, NB), 256, ATTN_SMEM>>>(qkvh, pad, o);
    attn_g1_kernel<<<dim3(NH, NB, 8), 256>>>(qkvh, pad, pm, ps, pa);
    attn_g2_kernel<<<dim3(NH, NB), 64>>>(pm, ps, pa, o);
    // 4. out projection + residual(x fp32) -> x1 (fp32)
    tgemm<2, float><<<dim3(DIM / 128, MROWS / 128), 256>>>(o, wo, opb, x, x1,
                                                           MROWS, DIM, DIM);
    // 5. pre-LN for FF -> half
    ln_kernel<<<MROWS, 128>>>(x1, l2g, l2b, f);
    // 6. FF1 + exact GELU -> half
    tgemm<1, __half><<<dim3(FFD / 128, MROWS / 128), 256>>>(f, w1h, b1, nullptr,
                                                            hh, MROWS, FFD, DIM);
    // 7. FF2 + residual(x1 fp32) -> final fp32 output
    tgemm<2, float><<<dim3(DIM / 128, MROWS / 128), 256>>>(hh, w2h, b2, x1, out,
                                                           MROWS, DIM, FFD);
}

// round 8
// speedup vs baseline: 6.3535x; 1.0654x over previous
#include <cuda_runtime.h>
#include <cuda_fp16.h>
#include <math.h>
#include <stdint.h>

#define SQ   2048
#define DIM  512
#define NH   8
#define HDIM 64
#define NB   4
#define WIN  64
#define MROWS (NB * SQ)        // 8192
#define QKVD (3 * DIM)         // 1536
#define FFD  2048

// ---------------- scratch ----------------------------------------------------
__device__ __half g_a   [(size_t)MROWS * DIM];
__device__ __half g_qkvh[(size_t)MROWS * QKVD];
__device__ __half g_o   [(size_t)MROWS * DIM];
__device__ float  g_x1  [(size_t)MROWS * DIM];
__device__ __half g_f   [(size_t)MROWS * DIM];
__device__ __half g_h   [(size_t)MROWS * FFD];
__device__ __half g_wqkv[(size_t)QKVD * DIM];
__device__ __half g_wo  [(size_t)DIM * DIM];
__device__ __half g_w1h [(size_t)FFD * DIM];
__device__ __half g_w2h [(size_t)DIM * FFD];
// split-softmax partials for query-0 global attention
__device__ float  g_pm  [NB * NH * 8];
__device__ float  g_ps  [NB * NH * 8];
__device__ float  g_pa  [NB * NH * 8 * HDIM];

// ---------------- helpers ----------------------------------------------------
__device__ __forceinline__ uint32_t smem_u32(const void* p) {
    return (uint32_t)__cvta_generic_to_shared(p);
}
__device__ __forceinline__ void ldsm_x4(uint32_t* r, uint32_t addr) {
    asm volatile("ldmatrix.sync.aligned.m8n8.x4.shared.b16 {%0,%1,%2,%3}, [%4];\n"
        : "=r"(r[0]), "=r"(r[1]), "=r"(r[2]), "=r"(r[3]) : "r"(addr));
}
__device__ __forceinline__ void ldsm_x2(uint32_t* r, uint32_t addr) {
    asm volatile("ldmatrix.sync.aligned.m8n8.x2.shared.b16 {%0,%1}, [%2];\n"
        : "=r"(r[0]), "=r"(r[1]) : "r"(addr));
}
__device__ __forceinline__ void ldsm_x2_trans(uint32_t* r, uint32_t addr) {
    asm volatile("ldmatrix.sync.aligned.m8n8.x2.trans.shared.b16 {%0,%1}, [%2];\n"
        : "=r"(r[0]), "=r"(r[1]) : "r"(addr));
}
__device__ __forceinline__ void mma16816(float* c, const uint32_t* a, const uint32_t* b) {
    asm volatile(
        "mma.sync.aligned.m16n8k16.row.col.f32.f16.f16.f32 "
        "{%0,%1,%2,%3},{%4,%5,%6,%7},{%8,%9},{%0,%1,%2,%3};\n"
        : "+f"(c[0]), "+f"(c[1]), "+f"(c[2]), "+f"(c[3])
        : "r"(a[0]), "r"(a[1]), "r"(a[2]), "r"(a[3]), "r"(b[0]), "r"(b[1]));
}
__device__ __forceinline__ void cp16(uint32_t saddr, const void* g) {
    asm volatile("cp.async.ca.shared.global [%0], [%1], 16;\n" :: "r"(saddr), "l"(g));
}
#define CP_COMMIT() asm volatile("cp.async.commit_group;\n" ::: "memory")
#define CP_WAIT0()  asm volatile("cp.async.wait_group 0;\n" ::: "memory")

__device__ __forceinline__ float gelu_exact(float v) {
    return 0.5f * v * (1.0f + erff(v * 0.70710678118654752f));
}
__device__ __forceinline__ void st2(float* p, float a, float b) { p[0] = a; p[1] = b; }
__device__ __forceinline__ void st2(__half* p, float a, float b) {
    *(__half2*)p = __floats2half2_rn(a, b);
}

// ---------------- fused fp32 -> fp16 weight convert --------------------------
#define N1 (QKVD * DIM)
#define N2 (DIM * DIM)
#define N3 (FFD * DIM)
#define N4 (DIM * FFD)
__global__ void f2h_all_kernel(const float* __restrict__ s1, __half* __restrict__ d1,
                               const float* __restrict__ s2, __half* __restrict__ d2,
                               const float* __restrict__ s3, __half* __restrict__ d3,
                               const float* __restrict__ s4, __half* __restrict__ d4) {
    int i = (blockIdx.x * blockDim.x + threadIdx.x) * 4;
    const float* s; __half* d;
    if (i < N1)                     { s = s1; d = d1; }
    else if ((i -= N1) < N2)        { s = s2; d = d2; }
    else if ((i -= N2) < N3)        { s = s3; d = d3; }
    else if ((i -= N3) < N4)        { s = s4; d = d4; }
    else return;
    float4 v = *(const float4*)(s + i);
    ((__half2*)d)[i / 2]     = __floats2half2_rn(v.x, v.y);
    ((__half2*)d)[i / 2 + 1] = __floats2half2_rn(v.z, v.w);
}

// ---------------- LayerNorm: float in, half out ------------------------------
__global__ void ln_kernel(const float* __restrict__ x, const float* __restrict__ g,
                          const float* __restrict__ bb, __half* __restrict__ out) {
    const int row = blockIdx.x;
    const int tid = threadIdx.x;
    const float4* xr = (const float4*)(x + (size_t)row * DIM);
    float4 v = xr[tid];
    float s  = v.x + v.y + v.z + v.w;
    float ss = v.x*v.x + v.y*v.y + v.z*v.z + v.w*v.w;
    #pragma unroll
    for (int o = 16; o > 0; o >>= 1) {
        s  += __shfl_xor_sync(0xffffffffu, s,  o);
        ss += __shfl_xor_sync(0xffffffffu, ss, o);
    }
    __shared__ float as_[4], ass_[4];
    if ((tid & 31) == 0) { as_[tid >> 5] = s; ass_[tid >> 5] = ss; }
    __syncthreads();
    s  = as_[0] + as_[1] + as_[2] + as_[3];
    ss = ass_[0] + ass_[1] + ass_[2] + ass_[3];
    const float mean = s * (1.0f / DIM);
    const float var  = ss * (1.0f / DIM) - mean * mean;
    const float inv  = rsqrtf(var + 1e-5f);
    float4 gv = ((const float4*)g)[tid];
    float4 bv = ((const float4*)bb)[tid];
    float r0 = (v.x - mean) * inv * gv.x + bv.x;
    float r1 = (v.y - mean) * inv * gv.y + bv.y;
    float r2 = (v.z - mean) * inv * gv.z + bv.z;
    float r3 = (v.w - mean) * inv * gv.w + bv.w;
    __half2* orow = (__half2*)(out + (size_t)row * DIM);
    orow[2 * tid]     = __floats2half2_rn(r0, r1);
    orow[2 * tid + 1] = __floats2half2_rn(r2, r3);
}

// ---------------- fp16 tensor-core GEMM (pipelined, proven R7) ---------------
#define LDK 20           // smem words (half2) per 32-half row (16 + pad 4)
#define STGW (128 * LDK) // words per stage

template <int EPI, typename OT>
__global__ __launch_bounds__(256)
void tgemm(const __half* __restrict__ A, const __half* __restrict__ W,
           const float* __restrict__ bias, const float* __restrict__ R,
           OT* __restrict__ C, int M, int N, int K) {
    __shared__ __align__(16) uint32_t As[2 * STGW];
    __shared__ __align__(16) uint32_t Bs[2 * STGW];

    const int tid  = threadIdx.x;
    const int warp = tid >> 5;
    const int lane = tid & 31;
    const int g    = lane >> 2;
    const int t4   = lane & 3;
    const int wm   = warp >> 2;
    const int wn   = warp & 3;

    const int bm = blockIdx.y * 128;
    const int bn = blockIdx.x * 128;

    const int lrow = tid >> 1;
    const __half* gA = A + (size_t)(bm + lrow) * K + (tid & 1) * 16;
    const __half* gB = W + (size_t)(bn + lrow) * K + (tid & 1) * 16;
    const uint32_t sA = smem_u32(As) + (lrow * LDK + (tid & 1) * 8) * 4;
    const uint32_t sB = smem_u32(Bs) + (lrow * LDK + (tid & 1) * 8) * 4;
    const int STGB = STGW * 4;

    const int l15 = lane & 15;
    const uint32_t aBase = smem_u32(As) +
        (((wm * 64 + l15) * LDK) + (lane >> 4) * 4) * 4;
    const uint32_t bBase = smem_u32(Bs) +
        (((wn * 32 + (l15 & 7)) * LDK) + ((l15 >> 3) * 4)) * 4;

    float acc[4][4][4];
    #pragma unroll
    for (int i = 0; i < 4; i++)
        #pragma unroll
        for (int j = 0; j < 4; j++)
            #pragma unroll
            for (int v = 0; v < 4; v++) acc[i][j][v] = 0.0f;

    const int NT = K / 32;
    cp16(sA, gA); cp16(sA + 16, gA + 8);
    cp16(sB, gB); cp16(sB + 16, gB + 8);
    CP_COMMIT();

    for (int t = 0; t < NT; t++) {
        CP_WAIT0();
        __syncthreads();
        if (t + 1 < NT) {
            const int s = (t + 1) & 1;
            const int k0 = (t + 1) * 32;
            cp16(sA + s * STGB, gA + k0); cp16(sA + s * STGB + 16, gA + k0 + 8);
            cp16(sB + s * STGB, gB + k0); cp16(sB + s * STGB + 16, gB + k0 + 8);
            CP_COMMIT();
        }
        const int sb = (t & 1) * STGB;
        #pragma unroll
        for (int kk = 0; kk < 2; kk++) {
            uint32_t af[4][4], bf[4][2];
            #pragma unroll
            for (int mt = 0; mt < 4; mt++)
                ldsm_x4(af[mt], aBase + sb + mt * (16 * LDK * 4) + kk * 32);
            #pragma unroll
            for (int nt = 0; nt < 4; nt++)
                ldsm_x2(bf[nt], bBase + sb + nt * (8 * LDK * 4) + kk * 32);
            #pragma unroll
            for (int mt = 0; mt < 4; mt++)
                #pragma unroll
                for (int nt = 0; nt < 4; nt++)
                    mma16816(acc[mt][nt], af[mt], bf[nt]);
        }
        __syncthreads();
    }

    #pragma unroll
    for (int mt = 0; mt < 4; mt++) {
        const int r0 = bm + wm * 64 + mt * 16 + g;
        const int r1 = r0 + 8;
        #pragma unroll
        for (int nt = 0; nt < 4; nt++) {
            const int col = bn + wn * 32 + nt * 8 + 2 * t4;
            const float b0 = bias[col], b1 = bias[col + 1];
            float v0 = acc[mt][nt][0] + b0;
            float v1 = acc[mt][nt][1] + b1;
            float v2 = acc[mt][nt][2] + b0;
            float v3 = acc[mt][nt][3] + b1;
            if (EPI == 1) {
                v0 = gelu_exact(v0); v1 = gelu_exact(v1);
                v2 = gelu_exact(v2); v3 = gelu_exact(v3);
            }
            if (EPI == 2) {
                v0 += R[(size_t)r0 * N + col];
                v1 += R[(size_t)r0 * N + col + 1];
                v2 += R[(size_t)r1 * N + col];
                v3 += R[(size_t)r1 * N + col + 1];
            }
            st2(C + (size_t)r0 * N + col, v0, v1);
            st2(C + (size_t)r1 * N + col, v2, v3);
        }
    }
}

// ---------------- Tiled local+global attention: QK^T and P.V both via MMA ----
// Block = 32 queries x (h, b). Key slots: {0} U [q0-64, q0+31+64] (<=161).
#define TQ    32
#define NKP   168   // K rows (score B-operand; ntmax*8 <= 168)
#define VROWS 176   // V rows (PV k-range padded to 16: 11*16 = 176)
#define LDA   36    // words (half2) per 64-half row: 32 + 4 pad
#define SP    172   // score row stride (floats)
#define LDP   184   // P row stride in halves (368B: conflict-free ldsm)
#define ATTN_SMEM (((32 + NKP + VROWS) * LDA + 32 * SP + 32 * LDP / 2) * 4 + 176 + 128)

__global__ __launch_bounds__(256)
void attn_tile_kernel(const __half* __restrict__ qkv,
                      const unsigned char* __restrict__ pad,
                      __half* __restrict__ o) {
    extern __shared__ __align__(16) uint32_t sm[];
    uint32_t* Qs  = sm;                          // 32*LDA
    uint32_t* Ksm = Qs + 32 * LDA;               // NKP*LDA
    uint32_t* Vsm = Ksm + NKP * LDA;             // VROWS*LDA
    float*    Sf  = (float*)(Vsm + VROWS * LDA); // 32*SP
    __half*   Ps  = (__half*)(Sf + 32 * SP);     // 32*LDP
    unsigned char* pads = (unsigned char*)(Ps + 32 * LDP);  // 176 B
    float*    invs = (float*)(pads + 176);       // 32 floats

    const int q0 = blockIdx.x * TQ;
    const int h  = blockIdx.y;
    const int b  = blockIdx.z;
    const int tid  = threadIdx.x;
    const int warp = tid >> 5;
    const int lane = tid & 31;
    const int g    = lane >> 2;
    const int t4   = lane & 3;

    int ks = q0 - WIN; if (ks < 0) ks = 0;
    int ke = q0 + TQ - 1 + WIN; if (ke > SQ - 1) ke = SQ - 1;
    const int hasg = (ks > 0) ? 1 : 0;
    const int nk = ke - ks + 1 + hasg;           // <= 161
    const int ntmax = (nk + 7) >> 3;
    const int NTK = (nk + 15) >> 4;              // PV k-tiles (<= 11)

    // ---- load Q tile (32 x 64 halves): 8 threads per row, uint4 (8 halves)
    {
        const int qrow = tid >> 3, l8 = tid & 7;
        const __half* src = qkv + ((size_t)(b * SQ + q0 + qrow)) * QKVD
                            + h * HDIM + l8 * 8;
        *(uint4*)(Qs + qrow * LDA + l8 * 4) = *(const uint4*)src;
    }
    // ---- load K/V slots (+ zero-fill V rows [nk, VROWS)) + pad flags ----
    {
        const int l8 = tid & 7;
        for (int j = tid >> 3; j < VROWS; j += 32) {
            if (j < nk) {
                const int kj = (hasg && j == 0) ? 0 : ks + j - hasg;
                const __half* base = qkv + ((size_t)(b * SQ + kj)) * QKVD;
                *(uint4*)(Ksm + j * LDA + l8 * 4) =
                    *(const uint4*)(base + DIM + h * HDIM + l8 * 8);
                *(uint4*)(Vsm + j * LDA + l8 * 4) =
                    *(const uint4*)(base + 2 * DIM + h * HDIM + l8 * 8);
                if (l8 == 0) pads[j] = pad[b * SQ + kj];
            } else {
                uint4 z = {0u, 0u, 0u, 0u};
                *(uint4*)(Vsm + j * LDA + l8 * 4) = z;
            }
        }
    }
    __syncthreads();

    // ---- scores S[32][nk] = Q @ K^T (fp16 MMA, fp32 accum) ----
    {
        const int mt = warp & 1;
        const int ng = warp >> 1;
        const int l15 = lane & 15;
        const uint32_t aAddr = smem_u32(Qs) +
            (((mt * 16 + l15) * LDA) + (lane >> 4) * 4) * 4;
        uint32_t af[4][4];
        #pragma unroll
        for (int kk = 0; kk < 4; kk++) ldsm_x4(af[kk], aAddr + kk * 32);

        const uint32_t bAddr = smem_u32(Ksm) +
            (((l15 & 7) * LDA) + (l15 >> 3) * 4) * 4;
        for (int nt = ng; nt < ntmax; nt += 4) {
            float c[4] = {0.f, 0.f, 0.f, 0.f};
            #pragma unroll
            for (int kk = 0; kk < 4; kk++) {
                uint32_t bf[2];
                ldsm_x2(bf, bAddr + nt * (8 * LDA * 4) + kk * 32);
                mma16816(c, af[kk], bf);
            }
            const int r0 = mt * 16 + g;
            const int col = nt * 8 + 2 * t4;
            Sf[r0 * SP + col]           = c[0];
            Sf[r0 * SP + col + 1]       = c[1];
            Sf[(r0 + 8) * SP + col]     = c[2];
            Sf[(r0 + 8) * SP + col + 1] = c[3];
        }
    }
    __syncthreads();

    // ---- softmax rows (8 threads/query) with window mask; emit P as fp16 ----
    {
        const int q = tid >> 3, sub = tid & 7;
        const int qg = q0 + q;
        float* Sr = Sf + q * SP;
        __half* Pr = Ps + q * LDP;
        float mx = -1e30f;
        for (int j = sub; j < nk; j += 8) {
            const int kj = (hasg && j == 0) ? 0 : ks + j - hasg;
            float s = Sr[j] * 0.125f;
            const int d = kj - qg;
            const bool valid = (kj == 0) || (d >= -WIN && d <= WIN);
            if (!valid || pads[j]) s = -1e30f;
            Sr[j] = s;
            mx = fmaxf(mx, s);
        }
        #pragma unroll
        for (int off = 4; off > 0; off >>= 1)
            mx = fmaxf(mx, __shfl_xor_sync(0xffffffffu, mx, off, 8));
        float sum = 0.f;
        const int jmax = NTK * 16;
        for (int j = sub; j < jmax; j += 8) {
            float e = 0.f;
            if (j < nk) { e = expf(Sr[j] - mx); sum += e; }
            Pr[j] = __float2half(e);
        }
        #pragma unroll
        for (int off = 4; off > 0; off >>= 1)
            sum += __shfl_xor_sync(0xffffffffu, sum, off, 8);
        if (sub == 0) invs[q] = 1.0f / sum;
    }
    __syncthreads();

    // ---- P @ V via MMA: A = P[32 x 16k] fp16, B = V^T via ldmatrix.trans ----
    {
        const int mt = warp >> 2;        // m-tile of 16 queries
        const int wn = warp & 3;         // n-tiles {wn, wn+4} (8 dims each)
        const int l15 = lane & 15;
        float c[2][4];
        #pragma unroll
        for (int t = 0; t < 2; t++)
            #pragma unroll
            for (int v = 0; v < 4; v++) c[t][v] = 0.f;

        const uint32_t aBase = smem_u32(Ps) +
            (mt * 16 + l15) * (LDP * 2) + (lane >> 4) * 16;
        const uint32_t vBase = smem_u32(Vsm) + l15 * (LDA * 4);
        for (int kk = 0; kk < NTK; kk++) {
            uint32_t a[4];
            ldsm_x4(a, aBase + kk * 32);
            #pragma unroll
            for (int t = 0; t < 2; t++) {
                const int nt = wn + t * 4;
                uint32_t bf[2];
                ldsm_x2_trans(bf, vBase + kk * 16 * (LDA * 4) + nt * 16);
                mma16816(c[t], a, bf);
            }
        }
        const int r0 = mt * 16 + g;
        const int r1 = r0 + 8;
        const float i0 = invs[r0], i1 = invs[r1];
        #pragma unroll
        for (int t = 0; t < 2; t++) {
            const int col = (wn + t * 4) * 8 + 2 * t4;
            __half2 h0 = __floats2half2_rn(c[t][0] * i0, c[t][1] * i0);
            __half2 h1 = __floats2half2_rn(c[t][2] * i1, c[t][3] * i1);
            *(__half2*)(o + ((size_t)(b * SQ + q0 + r0)) * DIM + h * HDIM + col) = h0;
            *(__half2*)(o + ((size_t)(b * SQ + q0 + r1)) * DIM + h * HDIM + col) = h1;
        }
    }
}

// ---------------- query-0 global attention: split-softmax --------------------
__global__ __launch_bounds__(256)
void attn_g1_kernel(const __half* __restrict__ qkv,
                    const unsigned char* __restrict__ pad,
                    float* __restrict__ pm, float* __restrict__ ps,
                    float* __restrict__ pa) {
    const int h = blockIdx.x, b = blockIdx.y, c = blockIdx.z;
    const int tid = threadIdx.x;
    const int idx = (b * NH + h) * 8 + c;
    __shared__ float qf[HDIM];
    __shared__ float S2[256];
    __shared__ float red[256];

    if (tid < HDIM)
        qf[tid] = __half2float(qkv[((size_t)(b * SQ)) * QKVD + h * HDIM + tid]);
    __syncthreads();

    const int j = c * 256 + tid;
    {
        const __half2* kp = (const __half2*)(qkv + ((size_t)(b * SQ + j)) * QKVD
                                             + DIM + h * HDIM);
        float s = 0.f;
        #pragma unroll
        for (int i = 0; i < 32; i++) {
            float2 f = __half22float2(kp[i]);
            s += qf[2 * i] * f.x + qf[2 * i + 1] * f.y;
        }
        s *= 0.125f;
        if (pad[b * SQ + j]) s = -1e30f;
        S2[tid] = s;
        red[tid] = s;
    }
    __syncthreads();
    for (int st = 128; st > 0; st >>= 1) {
        if (tid < st) red[tid] = fmaxf(red[tid], red[tid + st]);
        __syncthreads();
    }
    const float mx = red[0];
    __syncthreads();
    {
        float e = expf(S2[tid] - mx);
        S2[tid] = e;
        red[tid] = e;
    }
    __syncthreads();
    for (int st = 128; st > 0; st >>= 1) {
        if (tid < st) red[tid] += red[tid + st];
        __syncthreads();
    }
    if (tid == 0) { pm[idx] = mx; ps[idx] = red[0]; }
    __syncthreads();

    const int d = tid & 63, grp = tid >> 6;
    float acc = 0.f;
    for (int t = grp; t < 256; t += 4)
        acc += S2[t] * __half2float(qkv[((size_t)(b * SQ + c * 256 + t)) * QKVD
                                        + 2 * DIM + h * HDIM + d]);
    red[tid] = acc;
    __syncthreads();
    if (tid < HDIM)
        pa[(size_t)idx * HDIM + tid] =
            red[tid] + red[tid + 64] + red[tid + 128] + red[tid + 192];
}

__global__ __launch_bounds__(64)
void attn_g2_kernel(const float* __restrict__ pm, const float* __restrict__ ps,
                    const float* __restrict__ pa, __half* __restrict__ o) {
    const int h = blockIdx.x, b = blockIdx.y;
    const int d = threadIdx.x;
    const int base = (b * NH + h) * 8;
    float M = -1e30f;
    #pragma unroll
    for (int c = 0; c < 8; c++) M = fmaxf(M, pm[base + c]);
    float S = 0.f, acc = 0.f;
    #pragma unroll
    for (int c = 0; c < 8; c++) {
        const float w = expf(pm[base + c] - M);
        S   += ps[base + c] * w;
        acc += pa[(size_t)(base + c) * HDIM + d] * w;
    }
    o[((size_t)(b * SQ)) * DIM + h * HDIM + d] = __float2half(acc / S);
}

// ---------------- launch -----------------------------------------------------
extern "C" void kernel_launch(void* const* d_in, const int* in_sizes, int n_in,
                              void* d_out, int out_size) {
    const float* x   = (const float*)d_in[0];
    const unsigned char* pad = (const unsigned char*)d_in[1];
    const float* ipw = (const float*)d_in[3];
    const float* ipb = (const float*)d_in[4];
    const float* opw = (const float*)d_in[5];
    const float* opb = (const float*)d_in[6];
    const float* l1g = (const float*)d_in[7];
    const float* l1b = (const float*)d_in[8];
    const float* l2g = (const float*)d_in[9];
    const float* l2b = (const float*)d_in[10];
    const float* w1  = (const float*)d_in[11];
    const float* b1  = (const float*)d_in[12];
    const float* w2  = (const float*)d_in[13];
    const float* b2  = (const float*)d_in[14];
    float* out = (float*)d_out;

    __half *a, *qkvh, *o, *f, *hh, *wqkv, *wo, *w1h, *w2h;
    float *x1, *pm, *ps, *pa;
    cudaGetSymbolAddress((void**)&a,    g_a);
    cudaGetSymbolAddress((void**)&qkvh, g_qkvh);
    cudaGetSymbolAddress((void**)&o,    g_o);
    cudaGetSymbolAddress((void**)&x1,   g_x1);
    cudaGetSymbolAddress((void**)&f,    g_f);
    cudaGetSymbolAddress((void**)&hh,   g_h);
    cudaGetSymbolAddress((void**)&wqkv, g_wqkv);
    cudaGetSymbolAddress((void**)&wo,   g_wo);
    cudaGetSymbolAddress((void**)&w1h,  g_w1h);
    cudaGetSymbolAddress((void**)&w2h,  g_w2h);
    cudaGetSymbolAddress((void**)&pm,   g_pm);
    cudaGetSymbolAddress((void**)&ps,   g_ps);
    cudaGetSymbolAddress((void**)&pa,   g_pa);

    cudaFuncSetAttribute(attn_tile_kernel,
                         cudaFuncAttributeMaxDynamicSharedMemorySize, ATTN_SMEM);

    // fused weight conversion
    const int ntot = (N1 + N2 + N3 + N4) / 4;
    f2h_all_kernel<<<(ntot + 255) / 256, 256>>>(ipw, wqkv, opw, wo, w1, w1h, w2, w2h);

    // 1. pre-LN for attention -> half
    ln_kernel<<<MROWS, 128>>>(x, l1g, l1b, a);
    // 2. QKV projection (fp16 MMA) -> half
    tgemm<0, __half><<<dim3(QKVD / 128, MROWS / 128), 256>>>(a, wqkv, ipb, nullptr,
                                                             qkvh, MROWS, QKVD, DIM);
    // 3. attention: tiled local windows + q==0 global split-softmax fix-up
    attn_tile_kernel<<<dim3(SQ / TQ, NH, NB), 256, ATTN_SMEM>>>(qkvh, pad, o);
    attn_g1_kernel<<<dim3(NH, NB, 8), 256>>>(qkvh, pad, pm, ps, pa);
    attn_g2_kernel<<<dim3(NH, NB), 64>>>(pm, ps, pa, o);
    // 4. out projection + residual(x fp32) -> x1 (fp32)
    tgemm<2, float><<<dim3(DIM / 128, MROWS / 128), 256>>>(o, wo, opb, x, x1,
                                                           MROWS, DIM, DIM);
    // 5. pre-LN for FF -> half
    ln_kernel<<<MROWS, 128>>>(x1, l2g, l2b, f);
    // 6. FF1 + exact GELU -> half
    tgemm<1, __half><<<dim3(FFD / 128, MROWS / 128), 256>>>(f, w1h, b1, nullptr,
                                                            hh, MROWS, FFD, DIM);
    // 7. FF2 + residual(x1 fp32) -> final fp32 output
    tgemm<2, float><<<dim3(DIM / 128, MROWS / 128), 256>>>(hh, w2h, b2, x1, out,
                                                           MROWS, DIM, FFD);
}

// round 9
// speedup vs baseline: 6.6853x; 1.0522x over previous
#include <cuda_runtime.h>
#include <cuda_fp16.h>
#include <math.h>
#include <stdint.h>

#define SQ   2048
#define DIM  512
#define NH   8
#define HDIM 64
#define NB   4
#define WIN  64
#define MROWS (NB * SQ)        // 8192
#define QKVD (3 * DIM)         // 1536
#define FFD  2048
#define GCH  16                // key chunks for query-0 global attention

// ---------------- scratch ----------------------------------------------------
__device__ __half g_a   [(size_t)MROWS * DIM];
__device__ __half g_qkvh[(size_t)MROWS * QKVD];
__device__ __half g_o   [(size_t)MROWS * DIM];
__device__ float  g_x1  [(size_t)MROWS * DIM];
__device__ __half g_f   [(size_t)MROWS * DIM];
__device__ __half g_h   [(size_t)MROWS * FFD];
__device__ __half g_wqkv[(size_t)QKVD * DIM];
__device__ __half g_wo  [(size_t)DIM * DIM];
__device__ __half g_w1h [(size_t)FFD * DIM];
__device__ __half g_w2h [(size_t)DIM * FFD];
// split-softmax partials for query-0 global attention
__device__ float  g_pm  [NB * NH * GCH];
__device__ float  g_ps  [NB * NH * GCH];
__device__ float  g_pa  [NB * NH * GCH * HDIM];

// ---------------- helpers ----------------------------------------------------
__device__ __forceinline__ uint32_t smem_u32(const void* p) {
    return (uint32_t)__cvta_generic_to_shared(p);
}
__device__ __forceinline__ void ldsm_x4(uint32_t* r, uint32_t addr) {
    asm volatile("ldmatrix.sync.aligned.m8n8.x4.shared.b16 {%0,%1,%2,%3}, [%4];\n"
        : "=r"(r[0]), "=r"(r[1]), "=r"(r[2]), "=r"(r[3]) : "r"(addr));
}
__device__ __forceinline__ void ldsm_x2(uint32_t* r, uint32_t addr) {
    asm volatile("ldmatrix.sync.aligned.m8n8.x2.shared.b16 {%0,%1}, [%2];\n"
        : "=r"(r[0]), "=r"(r[1]) : "r"(addr));
}
__device__ __forceinline__ void ldsm_x2_trans(uint32_t* r, uint32_t addr) {
    asm volatile("ldmatrix.sync.aligned.m8n8.x2.trans.shared.b16 {%0,%1}, [%2];\n"
        : "=r"(r[0]), "=r"(r[1]) : "r"(addr));
}
__device__ __forceinline__ void mma16816(float* c, const uint32_t* a, const uint32_t* b) {
    asm volatile(
        "mma.sync.aligned.m16n8k16.row.col.f32.f16.f16.f32 "
        "{%0,%1,%2,%3},{%4,%5,%6,%7},{%8,%9},{%0,%1,%2,%3};\n"
        : "+f"(c[0]), "+f"(c[1]), "+f"(c[2]), "+f"(c[3])
        : "r"(a[0]), "r"(a[1]), "r"(a[2]), "r"(a[3]), "r"(b[0]), "r"(b[1]));
}
__device__ __forceinline__ void cp16(uint32_t saddr, const void* g) {
    asm volatile("cp.async.ca.shared.global [%0], [%1], 16;\n" :: "r"(saddr), "l"(g));
}
#define CP_COMMIT() asm volatile("cp.async.commit_group;\n" ::: "memory")
#define CP_WAIT0()  asm volatile("cp.async.wait_group 0;\n" ::: "memory")

__device__ __forceinline__ float gelu_exact(float v) {
    return 0.5f * v * (1.0f + erff(v * 0.70710678118654752f));
}
__device__ __forceinline__ void st2(float* p, float a, float b) { p[0] = a; p[1] = b; }
__device__ __forceinline__ void st2(__half* p, float a, float b) {
    *(__half2*)p = __floats2half2_rn(a, b);
}

// ---------------- fused fp32 -> fp16 weight convert --------------------------
#define N1 (QKVD * DIM)
#define N2 (DIM * DIM)
#define N3 (FFD * DIM)
#define N4 (DIM * FFD)
__global__ void f2h_all_kernel(const float* __restrict__ s1, __half* __restrict__ d1,
                               const float* __restrict__ s2, __half* __restrict__ d2,
                               const float* __restrict__ s3, __half* __restrict__ d3,
                               const float* __restrict__ s4, __half* __restrict__ d4) {
    int i = (blockIdx.x * blockDim.x + threadIdx.x) * 4;
    const float* s; __half* d;
    if (i < N1)                     { s = s1; d = d1; }
    else if ((i -= N1) < N2)        { s = s2; d = d2; }
    else if ((i -= N2) < N3)        { s = s3; d = d3; }
    else if ((i -= N3) < N4)        { s = s4; d = d4; }
    else return;
    float4 v = *(const float4*)(s + i);
    ((__half2*)d)[i / 2]     = __floats2half2_rn(v.x, v.y);
    ((__half2*)d)[i / 2 + 1] = __floats2half2_rn(v.z, v.w);
}

// ---------------- LayerNorm: float in, half out ------------------------------
__global__ void ln_kernel(const float* __restrict__ x, const float* __restrict__ g,
                          const float* __restrict__ bb, __half* __restrict__ out) {
    const int row = blockIdx.x;
    const int tid = threadIdx.x;
    const float4* xr = (const float4*)(x + (size_t)row * DIM);
    float4 v = xr[tid];
    float s  = v.x + v.y + v.z + v.w;
    float ss = v.x*v.x + v.y*v.y + v.z*v.z + v.w*v.w;
    #pragma unroll
    for (int o = 16; o > 0; o >>= 1) {
        s  += __shfl_xor_sync(0xffffffffu, s,  o);
        ss += __shfl_xor_sync(0xffffffffu, ss, o);
    }
    __shared__ float as_[4], ass_[4];
    if ((tid & 31) == 0) { as_[tid >> 5] = s; ass_[tid >> 5] = ss; }
    __syncthreads();
    s  = as_[0] + as_[1] + as_[2] + as_[3];
    ss = ass_[0] + ass_[1] + ass_[2] + ass_[3];
    const float mean = s * (1.0f / DIM);
    const float var  = ss * (1.0f / DIM) - mean * mean;
    const float inv  = rsqrtf(var + 1e-5f);
    float4 gv = ((const float4*)g)[tid];
    float4 bv = ((const float4*)bb)[tid];
    float r0 = (v.x - mean) * inv * gv.x + bv.x;
    float r1 = (v.y - mean) * inv * gv.y + bv.y;
    float r2 = (v.z - mean) * inv * gv.z + bv.z;
    float r3 = (v.w - mean) * inv * gv.w + bv.w;
    __half2* orow = (__half2*)(out + (size_t)row * DIM);
    orow[2 * tid]     = __floats2half2_rn(r0, r1);
    orow[2 * tid + 1] = __floats2half2_rn(r2, r3);
}

// ---------------- fp16 tensor-core GEMM (pipelined, proven R7/R8) ------------
#define LDK 20           // smem words (half2) per 32-half row (16 + pad 4)
#define STGW (128 * LDK) // words per stage

template <int EPI, typename OT>
__global__ __launch_bounds__(256)
void tgemm(const __half* __restrict__ A, const __half* __restrict__ W,
           const float* __restrict__ bias, const float* __restrict__ R,
           OT* __restrict__ C, int M, int N, int K) {
    __shared__ __align__(16) uint32_t As[2 * STGW];
    __shared__ __align__(16) uint32_t Bs[2 * STGW];

    const int tid  = threadIdx.x;
    const int warp = tid >> 5;
    const int lane = tid & 31;
    const int g    = lane >> 2;
    const int t4   = lane & 3;
    const int wm   = warp >> 2;
    const int wn   = warp & 3;

    const int bm = blockIdx.y * 128;
    const int bn = blockIdx.x * 128;

    const int lrow = tid >> 1;
    const __half* gA = A + (size_t)(bm + lrow) * K + (tid & 1) * 16;
    const __half* gB = W + (size_t)(bn + lrow) * K + (tid & 1) * 16;
    const uint32_t sA = smem_u32(As) + (lrow * LDK + (tid & 1) * 8) * 4;
    const uint32_t sB = smem_u32(Bs) + (lrow * LDK + (tid & 1) * 8) * 4;
    const int STGB = STGW * 4;

    const int l15 = lane & 15;
    const uint32_t aBase = smem_u32(As) +
        (((wm * 64 + l15) * LDK) + (lane >> 4) * 4) * 4;
    const uint32_t bBase = smem_u32(Bs) +
        (((wn * 32 + (l15 & 7)) * LDK) + ((l15 >> 3) * 4)) * 4;

    float acc[4][4][4];
    #pragma unroll
    for (int i = 0; i < 4; i++)
        #pragma unroll
        for (int j = 0; j < 4; j++)
            #pragma unroll
            for (int v = 0; v < 4; v++) acc[i][j][v] = 0.0f;

    const int NT = K / 32;
    cp16(sA, gA); cp16(sA + 16, gA + 8);
    cp16(sB, gB); cp16(sB + 16, gB + 8);
    CP_COMMIT();

    for (int t = 0; t < NT; t++) {
        CP_WAIT0();
        __syncthreads();
        if (t + 1 < NT) {
            const int s = (t + 1) & 1;
            const int k0 = (t + 1) * 32;
            cp16(sA + s * STGB, gA + k0); cp16(sA + s * STGB + 16, gA + k0 + 8);
            cp16(sB + s * STGB, gB + k0); cp16(sB + s * STGB + 16, gB + k0 + 8);
            CP_COMMIT();
        }
        const int sb = (t & 1) * STGB;
        #pragma unroll
        for (int kk = 0; kk < 2; kk++) {
            uint32_t af[4][4], bf[4][2];
            #pragma unroll
            for (int mt = 0; mt < 4; mt++)
                ldsm_x4(af[mt], aBase + sb + mt * (16 * LDK * 4) + kk * 32);
            #pragma unroll
            for (int nt = 0; nt < 4; nt++)
                ldsm_x2(bf[nt], bBase + sb + nt * (8 * LDK * 4) + kk * 32);
            #pragma unroll
            for (int mt = 0; mt < 4; mt++)
                #pragma unroll
                for (int nt = 0; nt < 4; nt++)
                    mma16816(acc[mt][nt], af[mt], bf[nt]);
        }
        __syncthreads();
    }

    #pragma unroll
    for (int mt = 0; mt < 4; mt++) {
        const int r0 = bm + wm * 64 + mt * 16 + g;
        const int r1 = r0 + 8;
        #pragma unroll
        for (int nt = 0; nt < 4; nt++) {
            const int col = bn + wn * 32 + nt * 8 + 2 * t4;
            const float b0 = bias[col], b1 = bias[col + 1];
            float v0 = acc[mt][nt][0] + b0;
            float v1 = acc[mt][nt][1] + b1;
            float v2 = acc[mt][nt][2] + b0;
            float v3 = acc[mt][nt][3] + b1;
            if (EPI == 1) {
                v0 = gelu_exact(v0); v1 = gelu_exact(v1);
                v2 = gelu_exact(v2); v3 = gelu_exact(v3);
            }
            if (EPI == 2) {
                v0 += R[(size_t)r0 * N + col];
                v1 += R[(size_t)r0 * N + col + 1];
                v2 += R[(size_t)r1 * N + col];
                v3 += R[(size_t)r1 * N + col + 1];
            }
            st2(C + (size_t)r0 * N + col, v0, v1);
            st2(C + (size_t)r1 * N + col, v2, v3);
        }
    }
}

// ---------------- Tiled attention: register softmax, MMA QK^T and P.V --------
// Block = 32 queries x (h, b). Key slots: {0} U [q0-64, q0+31+64] (<=161).
#define TQ    32
#define NKP   168   // K rows (score B-operand; ntmax*8 <= 168)
#define VROWS 176   // V rows (PV k-range padded to 16: 11*16 = 176)
#define LDA   36    // words (half2) per 64-half row: 32 + 4 pad
#define LDP   184   // P row stride in halves (368B)
#define ATTN_SMEM (((32 + NKP + VROWS) * LDA) * 4 + 32 * LDP * 2 + 2 * 128 * 4 + 192)

__global__ __launch_bounds__(256)
void attn_tile_kernel(const __half* __restrict__ qkv,
                      const unsigned char* __restrict__ pad,
                      __half* __restrict__ o) {
    extern __shared__ __align__(16) uint32_t sm[];
    uint32_t* Qs  = sm;                          // 32*LDA
    uint32_t* Ksm = Qs + 32 * LDA;               // NKP*LDA
    uint32_t* Vsm = Ksm + NKP * LDA;             // VROWS*LDA
    __half*   Ps  = (__half*)(Vsm + VROWS * LDA);// 32*LDP halves
    float*    pmax = (float*)(Ps + 32 * LDP);    // [32][4]
    float*    psum = pmax + 128;                 // [32][4]
    unsigned char* pads = (unsigned char*)(psum + 128);  // 176 B

    const int q0 = blockIdx.x * TQ;
    const int h  = blockIdx.y;
    const int b  = blockIdx.z;
    const int tid  = threadIdx.x;
    const int warp = tid >> 5;
    const int lane = tid & 31;
    const int g    = lane >> 2;
    const int t4   = lane & 3;

    int ks = q0 - WIN; if (ks < 0) ks = 0;
    int ke = q0 + TQ - 1 + WIN; if (ke > SQ - 1) ke = SQ - 1;
    const int hasg = (ks > 0) ? 1 : 0;
    const int nk = ke - ks + 1 + hasg;           // <= 161
    const int ntmax = (nk + 7) >> 3;
    const int NTK = (nk + 15) >> 4;              // PV k-tiles (<= 11)

    // ---- load Q tile (32 x 64 halves): 8 threads per row, uint4 (8 halves)
    {
        const int qrow = tid >> 3, l8 = tid & 7;
        const __half* src = qkv + ((size_t)(b * SQ + q0 + qrow)) * QKVD
                            + h * HDIM + l8 * 8;
        *(uint4*)(Qs + qrow * LDA + l8 * 4) = *(const uint4*)src;
    }
    // ---- load K/V slots (+ zero-fill V rows [nk, VROWS)) + pad flags ----
    {
        const int l8 = tid & 7;
        for (int j = tid >> 3; j < VROWS; j += 32) {
            if (j < nk) {
                const int kj = (hasg && j == 0) ? 0 : ks + j - hasg;
                const __half* base = qkv + ((size_t)(b * SQ + kj)) * QKVD;
                *(uint4*)(Ksm + j * LDA + l8 * 4) =
                    *(const uint4*)(base + DIM + h * HDIM + l8 * 8);
                *(uint4*)(Vsm + j * LDA + l8 * 4) =
                    *(const uint4*)(base + 2 * DIM + h * HDIM + l8 * 8);
                if (l8 == 0) pads[j] = pad[b * SQ + kj];
            } else {
                uint4 z = {0u, 0u, 0u, 0u};
                *(uint4*)(Vsm + j * LDA + l8 * 4) = z;
            }
        }
    }
    // ---- zero P tail columns [ntmax*8, NTK*16)  (<= 8 cols) ----
    {
        const int row = tid >> 3;
        const int cc = ntmax * 8 + (tid & 7);
        if (cc < NTK * 16) Ps[row * LDP + cc] = __float2half(0.f);
    }
    __syncthreads();

    // ---- scores (fp16 MMA) kept in registers; register softmax --------------
    {
        const int mt = warp & 1;          // m-tile of 16 queries
        const int ng = warp >> 1;         // n-tile stride group 0..3
        const int l15 = lane & 15;
        const uint32_t aAddr = smem_u32(Qs) +
            (((mt * 16 + l15) * LDA) + (lane >> 4) * 4) * 4;
        uint32_t af[4][4];
        #pragma unroll
        for (int kk = 0; kk < 4; kk++) ldsm_x4(af[kk], aAddr + kk * 32);

        const uint32_t bAddr = smem_u32(Ksm) +
            (((l15 & 7) * LDA) + (l15 >> 3) * 4) * 4;

        float cs[6][4];
        #pragma unroll
        for (int i = 0; i < 6; i++) {
            const int nt = ng + i * 4;
            cs[i][0] = cs[i][1] = cs[i][2] = cs[i][3] = 0.f;
            if (nt < ntmax) {
                #pragma unroll
                for (int kk = 0; kk < 4; kk++) {
                    uint32_t bf[2];
                    ldsm_x2(bf, bAddr + nt * (8 * LDA * 4) + kk * 32);
                    mma16816(cs[i], af[kk], bf);
                }
            }
        }

        // mask + row max (rows r0 = mt*16+g, r1 = r0+8)
        const int qg0 = q0 + mt * 16 + g;
        const int qg1 = qg0 + 8;
        float m0 = -1e30f, m1 = -1e30f;
        #pragma unroll
        for (int i = 0; i < 6; i++) {
            const int nt = ng + i * 4;
            if (nt < ntmax) {
                #pragma unroll
                for (int u = 0; u < 2; u++) {
                    const int col = nt * 8 + 2 * t4 + u;
                    const bool sv = col < nk;
                    const int kj = (hasg && col == 0) ? 0 : ks + col - hasg;
                    const bool pd = sv ? (pads[col] != 0) : true;
                    const int d0 = kj - qg0;
                    const bool v0 = sv && !pd && ((kj == 0) || (d0 >= -WIN && d0 <= WIN));
                    float s0 = v0 ? cs[i][u] * 0.125f : -1e30f;
                    cs[i][u] = s0; m0 = fmaxf(m0, s0);
                    const int d1 = kj - qg1;
                    const bool v1 = sv && !pd && ((kj == 0) || (d1 >= -WIN && d1 <= WIN));
                    float s1 = v1 ? cs[i][u + 2] * 0.125f : -1e30f;
                    cs[i][u + 2] = s1; m1 = fmaxf(m1, s1);
                }
            }
        }
        m0 = fmaxf(m0, __shfl_xor_sync(0xffffffffu, m0, 1));
        m0 = fmaxf(m0, __shfl_xor_sync(0xffffffffu, m0, 2));
        m1 = fmaxf(m1, __shfl_xor_sync(0xffffffffu, m1, 1));
        m1 = fmaxf(m1, __shfl_xor_sync(0xffffffffu, m1, 2));
        const int r0 = mt * 16 + g, r1 = r0 + 8;
        if (t4 == 0) { pmax[r0 * 4 + ng] = m0; pmax[r1 * 4 + ng] = m1; }
        __syncthreads();
        const float M0 = fmaxf(fmaxf(pmax[r0 * 4], pmax[r0 * 4 + 1]),
                               fmaxf(pmax[r0 * 4 + 2], pmax[r0 * 4 + 3]));
        const float M1 = fmaxf(fmaxf(pmax[r1 * 4], pmax[r1 * 4 + 1]),
                               fmaxf(pmax[r1 * 4 + 2], pmax[r1 * 4 + 3]));

        // exp + partial sums + write P (fp16)
        float s0 = 0.f, s1 = 0.f;
        #pragma unroll
        for (int i = 0; i < 6; i++) {
            const int nt = ng + i * 4;
            if (nt < ntmax) {
                const int col = nt * 8 + 2 * t4;
                float e0 = __expf(cs[i][0] - M0);
                float e1 = __expf(cs[i][1] - M0);
                float e2 = __expf(cs[i][2] - M1);
                float e3 = __expf(cs[i][3] - M1);
                s0 += e0 + e1; s1 += e2 + e3;
                *(__half2*)(Ps + r0 * LDP + col) = __floats2half2_rn(e0, e1);
                *(__half2*)(Ps + r1 * LDP + col) = __floats2half2_rn(e2, e3);
            }
        }
        s0 += __shfl_xor_sync(0xffffffffu, s0, 1);
        s0 += __shfl_xor_sync(0xffffffffu, s0, 2);
        s1 += __shfl_xor_sync(0xffffffffu, s1, 1);
        s1 += __shfl_xor_sync(0xffffffffu, s1, 2);
        if (t4 == 0) { psum[r0 * 4 + ng] = s0; psum[r1 * 4 + ng] = s1; }
    }
    __syncthreads();

    // ---- P @ V via MMA: A = P[32 x 16k] fp16, B = V^T via ldmatrix.trans ----
    {
        const int mt = warp >> 2;        // m-tile of 16 queries
        const int wn = warp & 3;         // n-tiles {wn, wn+4} (8 dims each)
        const int l15 = lane & 15;
        float c[2][4];
        #pragma unroll
        for (int t = 0; t < 2; t++)
            #pragma unroll
            for (int v = 0; v < 4; v++) c[t][v] = 0.f;

        const uint32_t aBase = smem_u32(Ps) +
            (mt * 16 + l15) * (LDP * 2) + (lane >> 4) * 16;
        const uint32_t vBase = smem_u32(Vsm) + l15 * (LDA * 4);
        for (int kk = 0; kk < NTK; kk++) {
            uint32_t a[4];
            ldsm_x4(a, aBase + kk * 32);
            #pragma unroll
            for (int t = 0; t < 2; t++) {
                const int nt = wn + t * 4;
                uint32_t bf[2];
                ldsm_x2_trans(bf, vBase + kk * 16 * (LDA * 4) + nt * 16);
                mma16816(c[t], a, bf);
            }
        }
        const int r0 = mt * 16 + g;
        const int r1 = r0 + 8;
        const float i0 = 1.f / (psum[r0 * 4] + psum[r0 * 4 + 1]
                                + psum[r0 * 4 + 2] + psum[r0 * 4 + 3]);
        const float i1 = 1.f / (psum[r1 * 4] + psum[r1 * 4 + 1]
                                + psum[r1 * 4 + 2] + psum[r1 * 4 + 3]);
        #pragma unroll
        for (int t = 0; t < 2; t++) {
            const int col = (wn + t * 4) * 8 + 2 * t4;
            __half2 h0 = __floats2half2_rn(c[t][0] * i0, c[t][1] * i0);
            __half2 h1 = __floats2half2_rn(c[t][2] * i1, c[t][3] * i1);
            *(__half2*)(o + ((size_t)(b * SQ + q0 + r0)) * DIM + h * HDIM + col) = h0;
            *(__half2*)(o + ((size_t)(b * SQ + q0 + r1)) * DIM + h * HDIM + col) = h1;
        }
    }
}

// ---------------- query-0 global attention: split-softmax (16 chunks) --------
__global__ __launch_bounds__(128)
void attn_g1_kernel(const __half* __restrict__ qkv,
                    const unsigned char* __restrict__ pad,
                    float* __restrict__ pm, float* __restrict__ ps,
                    float* __restrict__ pa) {
    const int h = blockIdx.x, b = blockIdx.y, c = blockIdx.z;
    const int tid = threadIdx.x;
    const int idx = (b * NH + h) * GCH + c;
    __shared__ float qf[HDIM];
    __shared__ float S2[128];
    __shared__ float red[128];

    if (tid < HDIM)
        qf[tid] = __half2float(qkv[((size_t)(b * SQ)) * QKVD + h * HDIM + tid]);
    __syncthreads();

    const int j = c * 128 + tid;
    {
        const __half2* kp = (const __half2*)(qkv + ((size_t)(b * SQ + j)) * QKVD
                                             + DIM + h * HDIM);
        float s = 0.f;
        #pragma unroll
        for (int i = 0; i < 32; i++) {
            float2 f = __half22float2(kp[i]);
            s += qf[2 * i] * f.x + qf[2 * i + 1] * f.y;
        }
        s *= 0.125f;
        if (pad[b * SQ + j]) s = -1e30f;
        S2[tid] = s;
        red[tid] = s;
    }
    __syncthreads();
    for (int st = 64; st > 0; st >>= 1) {
        if (tid < st) red[tid] = fmaxf(red[tid], red[tid + st]);
        __syncthreads();
    }
    const float mx = red[0];
    __syncthreads();
    {
        float e = __expf(S2[tid] - mx);
        S2[tid] = e;
        red[tid] = e;
    }
    __syncthreads();
    for (int st = 64; st > 0; st >>= 1) {
        if (tid < st) red[tid] += red[tid + st];
        __syncthreads();
    }
    if (tid == 0) { pm[idx] = mx; ps[idx] = red[0]; }
    __syncthreads();

    const int d = tid & 63, grp = tid >> 6;
    float acc = 0.f;
    for (int t = grp; t < 128; t += 2)
        acc += S2[t] * __half2float(qkv[((size_t)(b * SQ + c * 128 + t)) * QKVD
                                        + 2 * DIM + h * HDIM + d]);
    red[tid] = acc;
    __syncthreads();
    if (tid < HDIM)
        pa[(size_t)idx * HDIM + tid] = red[tid] + red[tid + 64];
}

__global__ __launch_bounds__(64)
void attn_g2_kernel(const float* __restrict__ pm, const float* __restrict__ ps,
                    const float* __restrict__ pa, __half* __restrict__ o) {
    const int h = blockIdx.x, b = blockIdx.y;
    const int d = threadIdx.x;
    const int base = (b * NH + h) * GCH;
    float M = -1e30f;
    #pragma unroll
    for (int c = 0; c < GCH; c++) M = fmaxf(M, pm[base + c]);
    float S = 0.f, acc = 0.f;
    #pragma unroll
    for (int c = 0; c < GCH; c++) {
        const float w = __expf(pm[base + c] - M);
        S   += ps[base + c] * w;
        acc += pa[(size_t)(base + c) * HDIM + d] * w;
    }
    o[((size_t)(b * SQ)) * DIM + h * HDIM + d] = __float2half(acc / S);
}

// ---------------- launch -----------------------------------------------------
extern "C" void kernel_launch(void* const* d_in, const int* in_sizes, int n_in,
                              void* d_out, int out_size) {
    const float* x   = (const float*)d_in[0];
    const unsigned char* pad = (const unsigned char*)d_in[1];
    const float* ipw = (const float*)d_in[3];
    const float* ipb = (const float*)d_in[4];
    const float* opw = (const float*)d_in[5];
    const float* opb = (const float*)d_in[6];
    const float* l1g = (const float*)d_in[7];
    const float* l1b = (const float*)d_in[8];
    const float* l2g = (const float*)d_in[9];
    const float* l2b = (const float*)d_in[10];
    const float* w1  = (const float*)d_in[11];
    const float* b1  = (const float*)d_in[12];
    const float* w2  = (const float*)d_in[13];
    const float* b2  = (const float*)d_in[14];
    float* out = (float*)d_out;

    __half *a, *qkvh, *o, *f, *hh, *wqkv, *wo, *w1h, *w2h;
    float *x1, *pm, *ps, *pa;
    cudaGetSymbolAddress((void**)&a,    g_a);
    cudaGetSymbolAddress((void**)&qkvh, g_qkvh);
    cudaGetSymbolAddress((void**)&o,    g_o);
    cudaGetSymbolAddress((void**)&x1,   g_x1);
    cudaGetSymbolAddress((void**)&f,    g_f);
    cudaGetSymbolAddress((void**)&hh,   g_h);
    cudaGetSymbolAddress((void**)&wqkv, g_wqkv);
    cudaGetSymbolAddress((void**)&wo,   g_wo);
    cudaGetSymbolAddress((void**)&w1h,  g_w1h);
    cudaGetSymbolAddress((void**)&w2h,  g_w2h);
    cudaGetSymbolAddress((void**)&pm,   g_pm);
    cudaGetSymbolAddress((void**)&ps,   g_ps);
    cudaGetSymbolAddress((void**)&pa,   g_pa);

    cudaFuncSetAttribute(attn_tile_kernel,
                         cudaFuncAttributeMaxDynamicSharedMemorySize, ATTN_SMEM);

    // fused weight conversion
    const int ntot = (N1 + N2 + N3 + N4) / 4;
    f2h_all_kernel<<<(ntot + 255) / 256, 256>>>(ipw, wqkv, opw, wo, w1, w1h, w2, w2h);

    // 1. pre-LN for attention -> half
    ln_kernel<<<MROWS, 128>>>(x, l1g, l1b, a);
    // 2. QKV projection (fp16 MMA) -> half
    tgemm<0, __half><<<dim3(QKVD / 128, MROWS / 128), 256>>>(a, wqkv, ipb, nullptr,
                                                             qkvh, MROWS, QKVD, DIM);
    // 3. attention: tiled local windows + q==0 global split-softmax fix-up
    attn_tile_kernel<<<dim3(SQ / TQ, NH, NB), 256, ATTN_SMEM>>>(qkvh, pad, o);
    attn_g1_kernel<<<dim3(NH, NB, GCH), 128>>>(qkvh, pad, pm, ps, pa);
    attn_g2_kernel<<<dim3(NH, NB), 64>>>(pm, ps, pa, o);
    // 4. out projection + residual(x fp32) -> x1 (fp32)
    tgemm<2, float><<<dim3(DIM / 128, MROWS / 128), 256>>>(o, wo, opb, x, x1,
                                                           MROWS, DIM, DIM);
    // 5. pre-LN for FF -> half
    ln_kernel<<<MROWS, 128>>>(x1, l2g, l2b, f);
    // 6. FF1 + exact GELU -> half
    tgemm<1, __half><<<dim3(FFD / 128, MROWS / 128), 256>>>(f, w1h, b1, nullptr,
                                                            hh, MROWS, FFD, DIM);
    // 7. FF2 + residual(x1 fp32) -> final fp32 output
    tgemm<2, float><<<dim3(DIM / 128, MROWS / 128), 256>>>(hh, w2h, b2, x1, out,
                                                           MROWS, DIM, FFD);
}

// round 10
// speedup vs baseline: 6.9527x; 1.0400x over previous
#include <cuda_runtime.h>
#include <cuda_fp16.h>
#include <math.h>
#include <stdint.h>

#define SQ   2048
#define DIM  512
#define NH   8
#define HDIM 64
#define NB   4
#define WIN  64
#define MROWS (NB * SQ)        // 8192
#define QKVD (3 * DIM)         // 1536
#define FFD  2048
#define GCH  16                // key chunks for query-0 global attention

// ---------------- scratch ----------------------------------------------------
__device__ __half g_a   [(size_t)MROWS * DIM];
__device__ __half g_qkvh[(size_t)MROWS * QKVD];
__device__ __half g_o   [(size_t)MROWS * DIM];
__device__ float  g_x1  [(size_t)MROWS * DIM];
__device__ __half g_f   [(size_t)MROWS * DIM];
__device__ __half g_h   [(size_t)MROWS * FFD];
__device__ __half g_wqkv[(size_t)QKVD * DIM];
__device__ __half g_wo  [(size_t)DIM * DIM];
__device__ __half g_w1h [(size_t)FFD * DIM];
__device__ __half g_w2h [(size_t)DIM * FFD];
// split-softmax partials for query-0 global attention
__device__ float  g_pm  [NB * NH * GCH];
__device__ float  g_ps  [NB * NH * GCH];
__device__ float  g_pa  [NB * NH * GCH * HDIM];

// ---------------- helpers ----------------------------------------------------
__device__ __forceinline__ uint32_t smem_u32(const void* p) {
    return (uint32_t)__cvta_generic_to_shared(p);
}
__device__ __forceinline__ void ldsm_x4(uint32_t* r, uint32_t addr) {
    asm volatile("ldmatrix.sync.aligned.m8n8.x4.shared.b16 {%0,%1,%2,%3}, [%4];\n"
        : "=r"(r[0]), "=r"(r[1]), "=r"(r[2]), "=r"(r[3]) : "r"(addr));
}
__device__ __forceinline__ void ldsm_x2(uint32_t* r, uint32_t addr) {
    asm volatile("ldmatrix.sync.aligned.m8n8.x2.shared.b16 {%0,%1}, [%2];\n"
        : "=r"(r[0]), "=r"(r[1]) : "r"(addr));
}
__device__ __forceinline__ void ldsm_x2_trans(uint32_t* r, uint32_t addr) {
    asm volatile("ldmatrix.sync.aligned.m8n8.x2.trans.shared.b16 {%0,%1}, [%2];\n"
        : "=r"(r[0]), "=r"(r[1]) : "r"(addr));
}
__device__ __forceinline__ void mma16816(float* c, const uint32_t* a, const uint32_t* b) {
    asm volatile(
        "mma.sync.aligned.m16n8k16.row.col.f32.f16.f16.f32 "
        "{%0,%1,%2,%3},{%4,%5,%6,%7},{%8,%9},{%0,%1,%2,%3};\n"
        : "+f"(c[0]), "+f"(c[1]), "+f"(c[2]), "+f"(c[3])
        : "r"(a[0]), "r"(a[1]), "r"(a[2]), "r"(a[3]), "r"(b[0]), "r"(b[1]));
}
__device__ __forceinline__ void cp16(uint32_t saddr, const void* g) {
    asm volatile("cp.async.ca.shared.global [%0], [%1], 16;\n" :: "r"(saddr), "l"(g));
}
#define CP_COMMIT() asm volatile("cp.async.commit_group;\n" ::: "memory")
#define CP_WAIT1()  asm volatile("cp.async.wait_group 1;\n" ::: "memory")

__device__ __forceinline__ float gelu_exact(float v) {
    return 0.5f * v * (1.0f + erff(v * 0.70710678118654752f));
}
__device__ __forceinline__ void st2(float* p, float a, float b) { p[0] = a; p[1] = b; }
__device__ __forceinline__ void st2(__half* p, float a, float b) {
    *(__half2*)p = __floats2half2_rn(a, b);
}

// ---------------- fused fp32 -> fp16 weight convert --------------------------
#define N1 (QKVD * DIM)
#define N2 (DIM * DIM)
#define N3 (FFD * DIM)
#define N4 (DIM * FFD)
__global__ void f2h_all_kernel(const float* __restrict__ s1, __half* __restrict__ d1,
                               const float* __restrict__ s2, __half* __restrict__ d2,
                               const float* __restrict__ s3, __half* __restrict__ d3,
                               const float* __restrict__ s4, __half* __restrict__ d4) {
    int i = (blockIdx.x * blockDim.x + threadIdx.x) * 4;
    const float* s; __half* d;
    if (i < N1)                     { s = s1; d = d1; }
    else if ((i -= N1) < N2)        { s = s2; d = d2; }
    else if ((i -= N2) < N3)        { s = s3; d = d3; }
    else if ((i -= N3) < N4)        { s = s4; d = d4; }
    else return;
    float4 v = *(const float4*)(s + i);
    ((__half2*)d)[i / 2]     = __floats2half2_rn(v.x, v.y);
    ((__half2*)d)[i / 2 + 1] = __floats2half2_rn(v.z, v.w);
}

// ---------------- LayerNorm: float in, half out ------------------------------
__global__ void ln_kernel(const float* __restrict__ x, const float* __restrict__ g,
                          const float* __restrict__ bb, __half* __restrict__ out) {
    const int row = blockIdx.x;
    const int tid = threadIdx.x;
    const float4* xr = (const float4*)(x + (size_t)row * DIM);
    float4 v = xr[tid];
    float s  = v.x + v.y + v.z + v.w;
    float ss = v.x*v.x + v.y*v.y + v.z*v.z + v.w*v.w;
    #pragma unroll
    for (int o = 16; o > 0; o >>= 1) {
        s  += __shfl_xor_sync(0xffffffffu, s,  o);
        ss += __shfl_xor_sync(0xffffffffu, ss, o);
    }
    __shared__ float as_[4], ass_[4];
    if ((tid & 31) == 0) { as_[tid >> 5] = s; ass_[tid >> 5] = ss; }
    __syncthreads();
    s  = as_[0] + as_[1] + as_[2] + as_[3];
    ss = ass_[0] + ass_[1] + ass_[2] + ass_[3];
    const float mean = s * (1.0f / DIM);
    const float var  = ss * (1.0f / DIM) - mean * mean;
    const float inv  = rsqrtf(var + 1e-5f);
    float4 gv = ((const float4*)g)[tid];
    float4 bv = ((const float4*)bb)[tid];
    float r0 = (v.x - mean) * inv * gv.x + bv.x;
    float r1 = (v.y - mean) * inv * gv.y + bv.y;
    float r2 = (v.z - mean) * inv * gv.z + bv.z;
    float r3 = (v.w - mean) * inv * gv.w + bv.w;
    __half2* orow = (__half2*)(out + (size_t)row * DIM);
    orow[2 * tid]     = __floats2half2_rn(r0, r1);
    orow[2 * tid + 1] = __floats2half2_rn(r2, r3);
}

// ---------------- fp16 tensor-core GEMM: 3-stage cp.async pipeline -----------
#define LDK 20           // smem words (half2) per 32-half row (16 + pad 4)
#define STGW (128 * LDK) // words per stage per operand
#define GEMM_SMEM (6 * STGW * 4)  // 3 stages x (A + B)

template <int EPI, typename OT>
__global__ __launch_bounds__(256)
void tgemm(const __half* __restrict__ A, const __half* __restrict__ W,
           const float* __restrict__ bias, const float* __restrict__ R,
           OT* __restrict__ C, int M, int N, int K) {
    extern __shared__ __align__(16) uint32_t dynsm[];
    uint32_t* As = dynsm;              // 3 * STGW
    uint32_t* Bs = dynsm + 3 * STGW;   // 3 * STGW

    const int tid  = threadIdx.x;
    const int warp = tid >> 5;
    const int lane = tid & 31;
    const int g    = lane >> 2;
    const int t4   = lane & 3;
    const int wm   = warp >> 2;
    const int wn   = warp & 3;

    const int bm = blockIdx.y * 128;
    const int bn = blockIdx.x * 128;

    const int lrow = tid >> 1;
    const __half* gA = A + (size_t)(bm + lrow) * K + (tid & 1) * 16;
    const __half* gB = W + (size_t)(bn + lrow) * K + (tid & 1) * 16;
    const uint32_t sA = smem_u32(As) + (lrow * LDK + (tid & 1) * 8) * 4;
    const uint32_t sB = smem_u32(Bs) + (lrow * LDK + (tid & 1) * 8) * 4;
    const int STGB = STGW * 4;         // stage stride in bytes

    const int l15 = lane & 15;
    const uint32_t aBase = smem_u32(As) +
        (((wm * 64 + l15) * LDK) + (lane >> 4) * 4) * 4;
    const uint32_t bBase = smem_u32(Bs) +
        (((wn * 32 + (l15 & 7)) * LDK) + ((l15 >> 3) * 4)) * 4;

    float acc[4][4][4];
    #pragma unroll
    for (int i = 0; i < 4; i++)
        #pragma unroll
        for (int j = 0; j < 4; j++)
            #pragma unroll
            for (int v = 0; v < 4; v++) acc[i][j][v] = 0.0f;

    const int NT = K / 32;             // >= 2 for all our shapes
    // prologue: stages 0 and 1
    cp16(sA, gA); cp16(sA + 16, gA + 8);
    cp16(sB, gB); cp16(sB + 16, gB + 8);
    CP_COMMIT();
    cp16(sA + STGB, gA + 32); cp16(sA + STGB + 16, gA + 40);
    cp16(sB + STGB, gB + 32); cp16(sB + STGB + 16, gB + 40);
    CP_COMMIT();

    int cs = 0;      // compute stage
    int pf = 2;      // prefetch stage
    for (int t = 0; t < NT; t++) {
        CP_WAIT1();          // stage t arrived (<=1 younger group pending)
        __syncthreads();     // visibility + all warps done with stage pf
        if (t + 2 < NT) {
            const int k0 = (t + 2) * 32;
            const int po = pf * STGB;
            cp16(sA + po, gA + k0); cp16(sA + po + 16, gA + k0 + 8);
            cp16(sB + po, gB + k0); cp16(sB + po + 16, gB + k0 + 8);
        }
        CP_COMMIT();         // commit every iter (possibly empty) -> uniform count
        const int sb = cs * STGB;
        #pragma unroll
        for (int kk = 0; kk < 2; kk++) {
            uint32_t af[4][4], bf[4][2];
            #pragma unroll
            for (int mt = 0; mt < 4; mt++)
                ldsm_x4(af[mt], aBase + sb + mt * (16 * LDK * 4) + kk * 32);
            #pragma unroll
            for (int nt = 0; nt < 4; nt++)
                ldsm_x2(bf[nt], bBase + sb + nt * (8 * LDK * 4) + kk * 32);
            #pragma unroll
            for (int mt = 0; mt < 4; mt++)
                #pragma unroll
                for (int nt = 0; nt < 4; nt++)
                    mma16816(acc[mt][nt], af[mt], bf[nt]);
        }
        cs = (cs == 2) ? 0 : cs + 1;
        pf = (pf == 2) ? 0 : pf + 1;
    }

    #pragma unroll
    for (int mt = 0; mt < 4; mt++) {
        const int r0 = bm + wm * 64 + mt * 16 + g;
        const int r1 = r0 + 8;
        #pragma unroll
        for (int nt = 0; nt < 4; nt++) {
            const int col = bn + wn * 32 + nt * 8 + 2 * t4;
            const float b0 = bias[col], b1 = bias[col + 1];
            float v0 = acc[mt][nt][0] + b0;
            float v1 = acc[mt][nt][1] + b1;
            float v2 = acc[mt][nt][2] + b0;
            float v3 = acc[mt][nt][3] + b1;
            if (EPI == 1) {
                v0 = gelu_exact(v0); v1 = gelu_exact(v1);
                v2 = gelu_exact(v2); v3 = gelu_exact(v3);
            }
            if (EPI == 2) {
                v0 += R[(size_t)r0 * N + col];
                v1 += R[(size_t)r0 * N + col + 1];
                v2 += R[(size_t)r1 * N + col];
                v3 += R[(size_t)r1 * N + col + 1];
            }
            st2(C + (size_t)r0 * N + col, v0, v1);
            st2(C + (size_t)r1 * N + col, v2, v3);
        }
    }
}

// ---------------- Tiled attention: register softmax, MMA QK^T and P.V --------
// Block = 32 queries x (h, b). Key slots: {0} U [q0-64, q0+31+64] (<=161).
#define TQ    32
#define NKP   168   // K rows (score B-operand; ntmax*8 <= 168)
#define VROWS 176   // V rows (PV k-range padded to 16: 11*16 = 176)
#define LDA   36    // words (half2) per 64-half row: 32 + 4 pad
#define LDP   184   // P row stride in halves (368B)
#define KJ_INVALID 0x40000000
#define ATTN_SMEM (((32 + NKP + VROWS) * LDA) * 4 + 32 * LDP * 2 + 2 * 128 * 4 + NKP * 4 + 64)

__global__ __launch_bounds__(256)
void attn_tile_kernel(const __half* __restrict__ qkv,
                      const unsigned char* __restrict__ pad,
                      __half* __restrict__ o) {
    extern __shared__ __align__(16) uint32_t sm[];
    uint32_t* Qs  = sm;                          // 32*LDA
    uint32_t* Ksm = Qs + 32 * LDA;               // NKP*LDA
    uint32_t* Vsm = Ksm + NKP * LDA;             // VROWS*LDA
    __half*   Ps  = (__half*)(Vsm + VROWS * LDA);// 32*LDP halves
    float*    pmax = (float*)(Ps + 32 * LDP);    // [32][4]
    float*    psum = pmax + 128;                 // [32][4]
    int*      kjs  = (int*)(psum + 128);         // [NKP] key index or sentinel

    const int q0 = blockIdx.x * TQ;
    const int h  = blockIdx.y;
    const int b  = blockIdx.z;
    const int tid  = threadIdx.x;
    const int warp = tid >> 5;
    const int lane = tid & 31;
    const int g    = lane >> 2;
    const int t4   = lane & 3;

    int ks = q0 - WIN; if (ks < 0) ks = 0;
    int ke = q0 + TQ - 1 + WIN; if (ke > SQ - 1) ke = SQ - 1;
    const int hasg = (ks > 0) ? 1 : 0;
    const int nk = ke - ks + 1 + hasg;           // <= 161
    const int ntmax = (nk + 7) >> 3;
    const int NTK = (nk + 15) >> 4;              // PV k-tiles (<= 11)

    // ---- load Q tile (32 x 64 halves): 8 threads per row, uint4 (8 halves)
    {
        const int qrow = tid >> 3, l8 = tid & 7;
        const __half* src = qkv + ((size_t)(b * SQ + q0 + qrow)) * QKVD
                            + h * HDIM + l8 * 8;
        *(uint4*)(Qs + qrow * LDA + l8 * 4) = *(const uint4*)src;
    }
    // ---- load K/V slots; build kjs[] (pad/bounds folded into sentinel) ------
    {
        const int l8 = tid & 7;
        for (int j = tid >> 3; j < VROWS; j += 32) {
            if (j < nk) {
                const int kj = (hasg && j == 0) ? 0 : ks + j - hasg;
                const __half* base = qkv + ((size_t)(b * SQ + kj)) * QKVD;
                *(uint4*)(Ksm + j * LDA + l8 * 4) =
                    *(const uint4*)(base + DIM + h * HDIM + l8 * 8);
                *(uint4*)(Vsm + j * LDA + l8 * 4) =
                    *(const uint4*)(base + 2 * DIM + h * HDIM + l8 * 8);
                if (l8 == 0) kjs[j] = pad[b * SQ + kj] ? KJ_INVALID : kj;
            } else {
                uint4 z = {0u, 0u, 0u, 0u};
                *(uint4*)(Vsm + j * LDA + l8 * 4) = z;
                if (l8 == 0 && j < NKP) kjs[j] = KJ_INVALID;
            }
        }
    }
    // ---- zero P tail columns [ntmax*8, NTK*16)  (<= 8 cols) ----
    {
        const int row = tid >> 3;
        const int cc = ntmax * 8 + (tid & 7);
        if (cc < NTK * 16) Ps[row * LDP + cc] = __float2half(0.f);
    }
    __syncthreads();

    // ---- scores (fp16 MMA) kept in registers; register softmax --------------
    {
        const int mt = warp & 1;          // m-tile of 16 queries
        const int ng = warp >> 1;         // n-tile stride group 0..3
        const int l15 = lane & 15;
        const uint32_t aAddr = smem_u32(Qs) +
            (((mt * 16 + l15) * LDA) + (lane >> 4) * 4) * 4;
        uint32_t af[4][4];
        #pragma unroll
        for (int kk = 0; kk < 4; kk++) ldsm_x4(af[kk], aAddr + kk * 32);

        const uint32_t bAddr = smem_u32(Ksm) +
            (((l15 & 7) * LDA) + (l15 >> 3) * 4) * 4;

        float cs[6][4];
        #pragma unroll
        for (int i = 0; i < 6; i++) {
            const int nt = ng + i * 4;
            cs[i][0] = cs[i][1] = cs[i][2] = cs[i][3] = 0.f;
            if (nt < ntmax) {
                #pragma unroll
                for (int kk = 0; kk < 4; kk++) {
                    uint32_t bf[2];
                    ldsm_x2(bf, bAddr + nt * (8 * LDA * 4) + kk * 32);
                    mma16816(cs[i], af[kk], bf);
                }
            }
        }

        // mask + row max (rows r0 = mt*16+g, r1 = r0+8)
        const int qg0 = q0 + mt * 16 + g;
        const int qg1 = qg0 + 8;
        float m0 = -1e30f, m1 = -1e30f;
        #pragma unroll
        for (int i = 0; i < 6; i++) {
            const int nt = ng + i * 4;
            if (nt < ntmax) {
                #pragma unroll
                for (int u = 0; u < 2; u++) {
                    const int col = nt * 8 + 2 * t4 + u;
                    const int kj = kjs[col];
                    const int d0 = kj - qg0;
                    const bool v0 = (kj == 0) || (d0 >= -WIN && d0 <= WIN);
                    float s0 = v0 ? cs[i][u] * 0.125f : -1e30f;
                    cs[i][u] = s0; m0 = fmaxf(m0, s0);
                    const int d1 = kj - qg1;
                    const bool v1 = (kj == 0) || (d1 >= -WIN && d1 <= WIN);
                    float s1 = v1 ? cs[i][u + 2] * 0.125f : -1e30f;
                    cs[i][u + 2] = s1; m1 = fmaxf(m1, s1);
                }
            }
        }
        m0 = fmaxf(m0, __shfl_xor_sync(0xffffffffu, m0, 1));
        m0 = fmaxf(m0, __shfl_xor_sync(0xffffffffu, m0, 2));
        m1 = fmaxf(m1, __shfl_xor_sync(0xffffffffu, m1, 1));
        m1 = fmaxf(m1, __shfl_xor_sync(0xffffffffu, m1, 2));
        const int r0 = mt * 16 + g, r1 = r0 + 8;
        if (t4 == 0) { pmax[r0 * 4 + ng] = m0; pmax[r1 * 4 + ng] = m1; }
        __syncthreads();
        const float M0 = fmaxf(fmaxf(pmax[r0 * 4], pmax[r0 * 4 + 1]),
                               fmaxf(pmax[r0 * 4 + 2], pmax[r0 * 4 + 3]));
        const float M1 = fmaxf(fmaxf(pmax[r1 * 4], pmax[r1 * 4 + 1]),
                               fmaxf(pmax[r1 * 4 + 2], pmax[r1 * 4 + 3]));

        // exp + partial sums + write P (fp16)
        float s0 = 0.f, s1 = 0.f;
        #pragma unroll
        for (int i = 0; i < 6; i++) {
            const int nt = ng + i * 4;
            if (nt < ntmax) {
                const int col = nt * 8 + 2 * t4;
                float e0 = __expf(cs[i][0] - M0);
                float e1 = __expf(cs[i][1] - M0);
                float e2 = __expf(cs[i][2] - M1);
                float e3 = __expf(cs[i][3] - M1);
                s0 += e0 + e1; s1 += e2 + e3;
                *(__half2*)(Ps + r0 * LDP + col) = __floats2half2_rn(e0, e1);
                *(__half2*)(Ps + r1 * LDP + col) = __floats2half2_rn(e2, e3);
            }
        }
        s0 += __shfl_xor_sync(0xffffffffu, s0, 1);
        s0 += __shfl_xor_sync(0xffffffffu, s0, 2);
        s1 += __shfl_xor_sync(0xffffffffu, s1, 1);
        s1 += __shfl_xor_sync(0xffffffffu, s1, 2);
        if (t4 == 0) { psum[r0 * 4 + ng] = s0; psum[r1 * 4 + ng] = s1; }
    }
    __syncthreads();

    // ---- P @ V via MMA: A = P[32 x 16k] fp16, B = V^T via ldmatrix.trans ----
    {
        const int mt = warp >> 2;        // m-tile of 16 queries
        const int wn = warp & 3;         // n-tiles {wn, wn+4} (8 dims each)
        const int l15 = lane & 15;
        float c[2][4];
        #pragma unroll
        for (int t = 0; t < 2; t++)
            #pragma unroll
            for (int v = 0; v < 4; v++) c[t][v] = 0.f;

        const uint32_t aBase = smem_u32(Ps) +
            (mt * 16 + l15) * (LDP * 2) + (lane >> 4) * 16;
        const uint32_t vBase = smem_u32(Vsm) + l15 * (LDA * 4);
        for (int kk = 0; kk < NTK; kk++) {
            uint32_t a[4];
            ldsm_x4(a, aBase + kk * 32);
            #pragma unroll
            for (int t = 0; t < 2; t++) {
                const int nt = wn + t * 4;
                uint32_t bf[2];
                ldsm_x2_trans(bf, vBase + kk * 16 * (LDA * 4) + nt * 16);
                mma16816(c[t], a, bf);
            }
        }
        const int r0 = mt * 16 + g;
        const int r1 = r0 + 8;
        const float i0 = 1.f / (psum[r0 * 4] + psum[r0 * 4 + 1]
                                + psum[r0 * 4 + 2] + psum[r0 * 4 + 3]);
        const float i1 = 1.f / (psum[r1 * 4] + psum[r1 * 4 + 1]
                                + psum[r1 * 4 + 2] + psum[r1 * 4 + 3]);
        #pragma unroll
        for (int t = 0; t < 2; t++) {
            const int col = (wn + t * 4) * 8 + 2 * t4;
            __half2 h0 = __floats2half2_rn(c[t][0] * i0, c[t][1] * i0);
            __half2 h1 = __floats2half2_rn(c[t][2] * i1, c[t][3] * i1);
            *(__half2*)(o + ((size_t)(b * SQ + q0 + r0)) * DIM + h * HDIM + col) = h0;
            *(__half2*)(o + ((size_t)(b * SQ + q0 + r1)) * DIM + h * HDIM + col) = h1;
        }
    }
}

// ---------------- query-0 global attention: split-softmax (16 chunks) --------
__global__ __launch_bounds__(128)
void attn_g1_kernel(const __half* __restrict__ qkv,
                    const unsigned char* __restrict__ pad,
                    float* __restrict__ pm, float* __restrict__ ps,
                    float* __restrict__ pa) {
    const int h = blockIdx.x, b = blockIdx.y, c = blockIdx.z;
    const int tid = threadIdx.x;
    const int idx = (b * NH + h) * GCH + c;
    __shared__ float qf[HDIM];
    __shared__ float S2[128];
    __shared__ float red[128];

    if (tid < HDIM)
        qf[tid] = __half2float(qkv[((size_t)(b * SQ)) * QKVD + h * HDIM + tid]);
    __syncthreads();

    const int j = c * 128 + tid;
    {
        const __half2* kp = (const __half2*)(qkv + ((size_t)(b * SQ + j)) * QKVD
                                             + DIM + h * HDIM);
        float s = 0.f;
        #pragma unroll
        for (int i = 0; i < 32; i++) {
            float2 f = __half22float2(kp[i]);
            s += qf[2 * i] * f.x + qf[2 * i + 1] * f.y;
        }
        s *= 0.125f;
        if (pad[b * SQ + j]) s = -1e30f;
        S2[tid] = s;
        red[tid] = s;
    }
    __syncthreads();
    for (int st = 64; st > 0; st >>= 1) {
        if (tid < st) red[tid] = fmaxf(red[tid], red[tid + st]);
        __syncthreads();
    }
    const float mx = red[0];
    __syncthreads();
    {
        float e = __expf(S2[tid] - mx);
        S2[tid] = e;
        red[tid] = e;
    }
    __syncthreads();
    for (int st = 64; st > 0; st >>= 1) {
        if (tid < st) red[tid] += red[tid + st];
        __syncthreads();
    }
    if (tid == 0) { pm[idx] = mx; ps[idx] = red[0]; }
    __syncthreads();

    const int d = tid & 63, grp = tid >> 6;
    float acc = 0.f;
    for (int t = grp; t < 128; t += 2)
        acc += S2[t] * __half2float(qkv[((size_t)(b * SQ + c * 128 + t)) * QKVD
                                        + 2 * DIM + h * HDIM + d]);
    red[tid] = acc;
    __syncthreads();
    if (tid < HDIM)
        pa[(size_t)idx * HDIM + tid] = red[tid] + red[tid + 64];
}

__global__ __launch_bounds__(64)
void attn_g2_kernel(const float* __restrict__ pm, const float* __restrict__ ps,
                    const float* __restrict__ pa, __half* __restrict__ o) {
    const int h = blockIdx.x, b = blockIdx.y;
    const int d = threadIdx.x;
    const int base = (b * NH + h) * GCH;
    float M = -1e30f;
    #pragma unroll
    for (int c = 0; c < GCH; c++) M = fmaxf(M, pm[base + c]);
    float S = 0.f, acc = 0.f;
    #pragma unroll
    for (int c = 0; c < GCH; c++) {
        const float w = __expf(pm[base + c] - M);
        S   += ps[base + c] * w;
        acc += pa[(size_t)(base + c) * HDIM + d] * w;
    }
    o[((size_t)(b * SQ)) * DIM + h * HDIM + d] = __float2half(acc / S);
}

// ---------------- launch -----------------------------------------------------
extern "C" void kernel_launch(void* const* d_in, const int* in_sizes, int n_in,
                              void* d_out, int out_size) {
    const float* x   = (const float*)d_in[0];
    const unsigned char* pad = (const unsigned char*)d_in[1];
    const float* ipw = (const float*)d_in[3];
    const float* ipb = (const float*)d_in[4];
    const float* opw = (const float*)d_in[5];
    const float* opb = (const float*)d_in[6];
    const float* l1g = (const float*)d_in[7];
    const float* l1b = (const float*)d_in[8];
    const float* l2g = (const float*)d_in[9];
    const float* l2b = (const float*)d_in[10];
    const float* w1  = (const float*)d_in[11];
    const float* b1  = (const float*)d_in[12];
    const float* w2  = (const float*)d_in[13];
    const float* b2  = (const float*)d_in[14];
    float* out = (float*)d_out;

    __half *a, *qkvh, *o, *f, *hh, *wqkv, *wo, *w1h, *w2h;
    float *x1, *pm, *ps, *pa;
    cudaGetSymbolAddress((void**)&a,    g_a);
    cudaGetSymbolAddress((void**)&qkvh, g_qkvh);
    cudaGetSymbolAddress((void**)&o,    g_o);
    cudaGetSymbolAddress((void**)&x1,   g_x1);
    cudaGetSymbolAddress((void**)&f,    g_f);
    cudaGetSymbolAddress((void**)&hh,   g_h);
    cudaGetSymbolAddress((void**)&wqkv, g_wqkv);
    cudaGetSymbolAddress((void**)&wo,   g_wo);
    cudaGetSymbolAddress((void**)&w1h,  g_w1h);
    cudaGetSymbolAddress((void**)&w2h,  g_w2h);
    cudaGetSymbolAddress((void**)&pm,   g_pm);
    cudaGetSymbolAddress((void**)&ps,   g_ps);
    cudaGetSymbolAddress((void**)&pa,   g_pa);

    cudaFuncSetAttribute(attn_tile_kernel,
                         cudaFuncAttributeMaxDynamicSharedMemorySize, ATTN_SMEM);
    cudaFuncSetAttribute(tgemm<0, __half>,
                         cudaFuncAttributeMaxDynamicSharedMemorySize, GEMM_SMEM);
    cudaFuncSetAttribute(tgemm<1, __half>,
                         cudaFuncAttributeMaxDynamicSharedMemorySize, GEMM_SMEM);
    cudaFuncSetAttribute(tgemm<2, float>,
                         cudaFuncAttributeMaxDynamicSharedMemorySize, GEMM_SMEM);

    // fused weight conversion
    const int ntot = (N1 + N2 + N3 + N4) / 4;
    f2h_all_kernel<<<(ntot + 255) / 256, 256>>>(ipw, wqkv, opw, wo, w1, w1h, w2, w2h);

    // 1. pre-LN for attention -> half
    ln_kernel<<<MROWS, 128>>>(x, l1g, l1b, a);
    // 2. QKV projection (fp16 MMA) -> half
    tgemm<0, __half><<<dim3(QKVD / 128, MROWS / 128), 256, GEMM_SMEM>>>(
        a, wqkv, ipb, nullptr, qkvh, MROWS, QKVD, DIM);
    // 3. attention: tiled local windows + q==0 global split-softmax fix-up
    attn_tile_kernel<<<dim3(SQ / TQ, NH, NB), 256, ATTN_SMEM>>>(qkvh, pad, o);
    attn_g1_kernel<<<dim3(NH, NB, GCH), 128>>>(qkvh, pad, pm, ps, pa);
    attn_g2_kernel<<<dim3(NH, NB), 64>>>(pm, ps, pa, o);
    // 4. out projection + residual(x fp32) -> x1 (fp32)
    tgemm<2, float><<<dim3(DIM / 128, MROWS / 128), 256, GEMM_SMEM>>>(
        o, wo, opb, x, x1, MROWS, DIM, DIM);
    // 5. pre-LN for FF -> half
    ln_kernel<<<MROWS, 128>>>(x1, l2g, l2b, f);
    // 6. FF1 + exact GELU -> half
    tgemm<1, __half><<<dim3(FFD / 128, MROWS / 128), 256, GEMM_SMEM>>>(
        f, w1h, b1, nullptr, hh, MROWS, FFD, DIM);
    // 7. FF2 + residual(x1 fp32) -> final fp32 output
    tgemm<2, float><<<dim3(DIM / 128, MROWS / 128), 256, GEMM_SMEM>>>(
        hh, w2h, b2, x1, out, MROWS, DIM, FFD);
}